// round 2
// baseline (speedup 1.0000x reference)
#include <cuda_runtime.h>

#define HD   64
#define TPB  128

// Dynamic SMEM layout (float4-aligned):
//   sWt4 : 1024 float4 (W_tau rows, 16 float4/row)      offset 0
//   sWh4 : 1024 float4 (W_h rows)                        offset 1024
//   sUt4 :   64 float4 {U_tau[g][0..2], b_tau[g]}        offset 2048
//   sUh4 :   64 float4 {U_h[g][0..2],  b_h[g]}           offset 2112
//   sWo4 :   48 float4 (W_out rows, 16 float4/row)       offset 2176
//   hn_s : 128*64 float (per-thread column bounce)       offset 2224 (in float4 units)
#define SMEM_F4_WEIGHTS 2224
#define SMEM_BYTES (SMEM_F4_WEIGHTS * 16 + TPB * HD * 4)

// Accumulate one float4 chunk of both matvecs (W_tau row g and W_h row g).
#define ACC(K, HV)                                        \
    {                                                     \
        const float4 wt = sWt4[gbase + (K)];              \
        const float4 wh = sWh4[gbase + (K)];              \
        at0 = fmaf(wt.x, HV.x, at0);                      \
        at1 = fmaf(wt.y, HV.y, at1);                      \
        at2 = fmaf(wt.z, HV.z, at2);                      \
        at3 = fmaf(wt.w, HV.w, at3);                      \
        af0 = fmaf(wh.x, HV.x, af0);                      \
        af1 = fmaf(wh.y, HV.y, af1);                      \
        af2 = fmaf(wh.z, HV.z, af2);                      \
        af3 = fmaf(wh.w, HV.w, af3);                      \
    }

// Readout accumulate (W_out row o).
#define ACCO(K, HV)                                       \
    {                                                     \
        const float4 w = sWo4[o * 16 + (K)];              \
        a0 = fmaf(w.x, HV.x, a0);                         \
        a1 = fmaf(w.y, HV.y, a1);                         \
        a2 = fmaf(w.z, HV.z, a2);                         \
        a3 = fmaf(w.w, HV.w, a3);                         \
    }

// Reload one float4 of h from the SMEM bounce buffer.
#define LOADH(V, G0)                                      \
    V.x = hn_s[(G0 + 0) * TPB + t];                       \
    V.y = hn_s[(G0 + 1) * TPB + t];                       \
    V.z = hn_s[(G0 + 2) * TPB + t];                       \
    V.w = hn_s[(G0 + 3) * TPB + t];

__global__ void __launch_bounds__(TPB, 3) liquid_ode_kernel(
    const float* __restrict__ coords,   // (B*N, 3)
    const float* __restrict__ W_h,      // (64,64)
    const float* __restrict__ U_h,      // (64,3)
    const float* __restrict__ b_h,      // (64)
    const float* __restrict__ W_tau,    // (64,64)
    const float* __restrict__ U_tau,    // (64,3)
    const float* __restrict__ b_tau,    // (64)
    const float* __restrict__ W_out,    // (3,64)
    const float* __restrict__ b_out,    // (3)
    float* __restrict__ out,            // (B,3,N)
    int npts, int N)
{
    extern __shared__ float4 smem4[];
    float4* sWt4 = smem4;
    float4* sWh4 = smem4 + 1024;
    float4* sUt4 = smem4 + 2048;
    float4* sUh4 = smem4 + 2112;
    float4* sWo4 = smem4 + 2176;
    float*  hn_s = reinterpret_cast<float*>(smem4 + SMEM_F4_WEIGHTS);

    const int t = threadIdx.x;

    for (int i = t; i < 1024; i += TPB) {
        sWt4[i] = reinterpret_cast<const float4*>(W_tau)[i];
        sWh4[i] = reinterpret_cast<const float4*>(W_h)[i];
    }
    if (t < HD) {
        sUt4[t] = make_float4(U_tau[t*3+0], U_tau[t*3+1], U_tau[t*3+2], b_tau[t]);
        sUh4[t] = make_float4(U_h[t*3+0],  U_h[t*3+1],  U_h[t*3+2],  b_h[t]);
    }
    if (t < 48)
        sWo4[t] = reinterpret_cast<const float4*>(W_out)[t];
    __syncthreads();

    const int p = blockIdx.x * TPB + t;
    if (p >= npts) return;

    const float cx = coords[3*p + 0];
    const float cy = coords[3*p + 1];
    const float cz = coords[3*p + 2];

    // Hidden state: 16 named float4 (cannot demote to local).
    float4 h0, h1, h2, h3, h4, h5, h6, h7, h8, h9, h10, h11, h12, h13, h14, h15;
    const float4 z4 = make_float4(0.f, 0.f, 0.f, 0.f);
    h0=z4; h1=z4; h2=z4; h3=z4; h4=z4; h5=z4; h6=z4; h7=z4;
    h8=z4; h9=z4; h10=z4; h11=z4; h12=z4; h13=z4; h14=z4; h15=z4;

    #pragma unroll 1
    for (int s = 0; s < 8; s++) {
        #pragma unroll 1
        for (int g = 0; g < HD; g++) {
            const int gbase = g * 16;
            const float4 ut = sUt4[g];
            const float4 uh = sUh4[g];
            float at0 = fmaf(ut.x, cx, ut.w);
            at0 = fmaf(ut.y, cy, at0);
            at0 = fmaf(ut.z, cz, at0);
            float af0 = fmaf(uh.x, cx, uh.w);
            af0 = fmaf(uh.y, cy, af0);
            af0 = fmaf(uh.z, cz, af0);
            float at1 = 0.f, at2 = 0.f, at3 = 0.f;
            float af1 = 0.f, af2 = 0.f, af3 = 0.f;

            ACC( 0, h0)  ACC( 1, h1)  ACC( 2, h2)  ACC( 3, h3)
            ACC( 4, h4)  ACC( 5, h5)  ACC( 6, h6)  ACC( 7, h7)
            ACC( 8, h8)  ACC( 9, h9)  ACC(10, h10) ACC(11, h11)
            ACC(12, h12) ACC(13, h13) ACC(14, h14) ACC(15, h15)

            float ta = (at0 + at1) + (at2 + at3);
            float fa = (af0 + af1) + (af2 + af3);

            // tau = 0.1 + softplus(clip(ta,-50,50)) * 9.9
            ta = fminf(fmaxf(ta, -50.0f), 50.0f);
            const float sp  = fmaxf(ta, 0.0f) + log1pf(__expf(-fabsf(ta)));
            const float tau = fmaf(sp, 9.9f, 0.1f);

            // f = sigmoid(fa)
            const float fsig = __fdividef(1.0f, 1.0f + __expf(-fa));

            // hold = component g of old h (select from named vars)
            const float* hv = &h0.x;   // h0..h15 are consecutive? NOT guaranteed.
            (void)hv;
            float hold;
            {
                const int q = g >> 2, r = g & 3;
                float4 hq;
                switch (q) {
                    case 0:  hq = h0;  break; case 1:  hq = h1;  break;
                    case 2:  hq = h2;  break; case 3:  hq = h3;  break;
                    case 4:  hq = h4;  break; case 5:  hq = h5;  break;
                    case 6:  hq = h6;  break; case 7:  hq = h7;  break;
                    case 8:  hq = h8;  break; case 9:  hq = h9;  break;
                    case 10: hq = h10; break; case 11: hq = h11; break;
                    case 12: hq = h12; break; case 13: hq = h13; break;
                    case 14: hq = h14; break; default: hq = h15; break;
                }
                hold = (r == 0) ? hq.x : (r == 1) ? hq.y : (r == 2) ? hq.z : hq.w;
            }

            // Euler: h' = h + dt * (f - h/tau)
            hn_s[g * TPB + t] = hold + 0.125f * (fsig - hold * __fdividef(1.0f, tau));
        }
        // copy hn back into registers (column-private: no sync needed)
        LOADH(h0,   0) LOADH(h1,   4) LOADH(h2,   8) LOADH(h3,  12)
        LOADH(h4,  16) LOADH(h5,  20) LOADH(h6,  24) LOADH(h7,  28)
        LOADH(h8,  32) LOADH(h9,  36) LOADH(h10, 40) LOADH(h11, 44)
        LOADH(h12, 48) LOADH(h13, 52) LOADH(h14, 56) LOADH(h15, 60)
    }

    // readout: v = tanh(W_out @ h + b_out) * 10
    float v[3];
    #pragma unroll
    for (int o = 0; o < 3; o++) {
        float a0 = 0.f, a1 = 0.f, a2 = 0.f, a3 = 0.f;
        ACCO( 0, h0)  ACCO( 1, h1)  ACCO( 2, h2)  ACCO( 3, h3)
        ACCO( 4, h4)  ACCO( 5, h5)  ACCO( 6, h6)  ACCO( 7, h7)
        ACCO( 8, h8)  ACCO( 9, h9)  ACCO(10, h10) ACCO(11, h11)
        ACCO(12, h12) ACCO(13, h13) ACCO(14, h14) ACCO(15, h15)
        v[o] = tanhf((a0 + a1) + (a2 + a3) + __ldg(&b_out[o])) * 10.0f;
    }

    const int b = p / N;
    const int n = p - b * N;
    out[(b*3 + 0) * N + n] = v[0];
    out[(b*3 + 1) * N + n] = v[1];
    out[(b*3 + 2) * N + n] = v[2];
}

extern "C" void kernel_launch(void* const* d_in, const int* in_sizes, int n_in,
                              void* d_out, int out_size) {
    const float* coords = (const float*)d_in[0];
    const float* W_h    = (const float*)d_in[1];
    const float* U_h    = (const float*)d_in[2];
    const float* b_h    = (const float*)d_in[3];
    const float* W_tau  = (const float*)d_in[4];
    const float* U_tau  = (const float*)d_in[5];
    const float* b_tau  = (const float*)d_in[6];
    const float* W_out  = (const float*)d_in[7];
    const float* b_out  = (const float*)d_in[8];
    float* out = (float*)d_out;

    const int npts = in_sizes[0] / 3;   // B * N
    const int B    = 2;
    const int N    = npts / B;

    static int smem_set = -1;
    if (smem_set < 0) {
        cudaFuncSetAttribute(liquid_ode_kernel,
                             cudaFuncAttributeMaxDynamicSharedMemorySize,
                             SMEM_BYTES);
        smem_set = 1;
    }

    const int grid = (npts + TPB - 1) / TPB;
    liquid_ode_kernel<<<grid, TPB, SMEM_BYTES>>>(coords,
                                                 W_h, U_h, b_h,
                                                 W_tau, U_tau, b_tau,
                                                 W_out, b_out,
                                                 out, npts, N);
}

// round 3
// speedup vs baseline: 1.2822x; 1.2822x over previous
#include <cuda_runtime.h>

#define HD   64
#define TPB  128

// ---- packed f32x2 helpers (Blackwell sm_103a) ----
#define FMA2(d, a, b, c) \
    asm("fma.rn.f32x2 %0, %1, %2, %3;" : "=l"(d) : "l"(a), "l"(b), "l"(c))
#define ADD2(d, a, b) \
    asm("add.rn.f32x2 %0, %1, %2;" : "=l"(d) : "l"(a), "l"(b))
#define PACK2(d, lo, hi) \
    asm("mov.b64 %0, {%1, %2};" : "=l"(d) : "f"(lo), "f"(hi))
#define UNPACK2(lo, hi, s) \
    asm("mov.b64 {%0, %1}, %2;" : "=f"(lo), "=f"(hi) : "l"(s))

typedef unsigned long long u64t;

// SMEM byte offsets
#define OFF_WT   0                        // W_tau  64x64 f32      (16384 B)
#define OFF_WH   16384                    // W_h    64x64 f32      (16384 B)
#define OFF_U2   32768                    // per-g {utx,uhx}{uty,uhy}{utz,uhz}{bt,bh} (2048 B)
#define OFF_WO   34816                    // W_out  3x64 f32       (768 B, pad 1024)
#define OFF_BOUNCE 35840                  // h bounce: 32 u64 pairs x TPB (32768 B)
#define SMEM_BYTES (OFF_BOUNCE + TPB * 32 * 8)

// One 16-byte chunk of both weight rows: 4 floats = 2 packed pairs each.
#define KROW(J, HA, HB, T0, T1, F0, F1)                         \
    {                                                           \
        const ulonglong2 wt = sWt2[gb + (J)];                   \
        const ulonglong2 wh = sWh2[gb + (J)];                   \
        FMA2(T0, wt.x, HA, T0);                                 \
        FMA2(T1, wt.y, HB, T1);                                 \
        FMA2(F0, wh.x, HA, F0);                                 \
        FMA2(F1, wh.y, HB, F1);                                 \
    }

#define OROW(J, HA, HB)                                         \
    {                                                           \
        const ulonglong2 w = sWo2[o * 16 + (J)];                \
        FMA2(a0, w.x, HA, a0);                                  \
        FMA2(a1, w.y, HB, a1);                                  \
    }

#define LOADH2(V, P)  V = bounce64[(P) * TPB + t];

__global__ void __launch_bounds__(TPB, 3) liquid_ode_kernel(
    const float* __restrict__ coords,
    const float* __restrict__ W_h,
    const float* __restrict__ U_h,
    const float* __restrict__ b_h,
    const float* __restrict__ W_tau,
    const float* __restrict__ U_tau,
    const float* __restrict__ b_tau,
    const float* __restrict__ W_out,
    const float* __restrict__ b_out,
    float* __restrict__ out,
    int npts, int N)
{
    extern __shared__ char smem[];
    const ulonglong2* sWt2 = reinterpret_cast<const ulonglong2*>(smem + OFF_WT);
    const ulonglong2* sWh2 = reinterpret_cast<const ulonglong2*>(smem + OFF_WH);
    const ulonglong2* sU22 = reinterpret_cast<const ulonglong2*>(smem + OFF_U2);
    const ulonglong2* sWo2 = reinterpret_cast<const ulonglong2*>(smem + OFF_WO);
    u64t*  bounce64 = reinterpret_cast<u64t*>(smem + OFF_BOUNCE);
    float* bounce_f = reinterpret_cast<float*>(smem + OFF_BOUNCE);

    const int t = threadIdx.x;

    // ---- stage weights ----
    {
        float4* dWt = reinterpret_cast<float4*>(smem + OFF_WT);
        float4* dWh = reinterpret_cast<float4*>(smem + OFF_WH);
        for (int i = t; i < 1024; i += TPB) {
            dWt[i] = reinterpret_cast<const float4*>(W_tau)[i];
            dWh[i] = reinterpret_cast<const float4*>(W_h)[i];
        }
        float* dU = reinterpret_cast<float*>(smem + OFF_U2);
        if (t < HD) {
            dU[t*8 + 0] = U_tau[t*3 + 0]; dU[t*8 + 1] = U_h[t*3 + 0];
            dU[t*8 + 2] = U_tau[t*3 + 1]; dU[t*8 + 3] = U_h[t*3 + 1];
            dU[t*8 + 4] = U_tau[t*3 + 2]; dU[t*8 + 5] = U_h[t*3 + 2];
            dU[t*8 + 6] = b_tau[t];       dU[t*8 + 7] = b_h[t];
        }
        float4* dWo = reinterpret_cast<float4*>(smem + OFF_WO);
        if (t < 48)
            dWo[t] = reinterpret_cast<const float4*>(W_out)[t];
    }
    __syncthreads();

    const int p = blockIdx.x * TPB + t;
    if (p >= npts) return;

    const float cx = coords[3*p + 0];
    const float cy = coords[3*p + 1];
    const float cz = coords[3*p + 2];
    u64t CXX, CYY, CZZ;
    PACK2(CXX, cx, cx);
    PACK2(CYY, cy, cy);
    PACK2(CZZ, cz, cz);

    // h as 32 packed pairs (named: cannot demote to local)
    u64t H0,H1,H2,H3,H4,H5,H6,H7,H8,H9,H10,H11,H12,H13,H14,H15,
         H16,H17,H18,H19,H20,H21,H22,H23,H24,H25,H26,H27,H28,H29,H30,H31;
    H0=0;H1=0;H2=0;H3=0;H4=0;H5=0;H6=0;H7=0;H8=0;H9=0;H10=0;H11=0;H12=0;H13=0;H14=0;H15=0;
    H16=0;H17=0;H18=0;H19=0;H20=0;H21=0;H22=0;H23=0;H24=0;H25=0;H26=0;H27=0;H28=0;H29=0;H30=0;H31=0;

    // bounce holds h(prev step) scalars; init to h0 = 0 (thread-private column)
    #pragma unroll
    for (int q = 0; q < 32; q++) bounce64[q * TPB + t] = 0ull;

    #pragma unroll 1
    for (int s = 0; s < 8; s++) {
        #pragma unroll 1
        for (int g = 0; g < HD; g++) {
            const int gb = g * 16;

            // input projections: uacc = {tau_acc, f_acc}
            const ulonglong2 u01 = sU22[g*2 + 0];
            const ulonglong2 u23 = sU22[g*2 + 1];
            u64t uacc = u23.y;                 // {b_tau[g], b_h[g]}
            FMA2(uacc, u01.x, CXX, uacc);
            FMA2(uacc, u01.y, CYY, uacc);
            FMA2(uacc, u23.x, CZZ, uacc);

            u64t at0 = 0, at1 = 0, at2 = 0, at3 = 0;
            u64t af0 = 0, af1 = 0, af2 = 0, af3 = 0;

            KROW( 0, H0,  H1,  at0, at1, af0, af1)
            KROW( 1, H2,  H3,  at2, at3, af2, af3)
            KROW( 2, H4,  H5,  at0, at1, af0, af1)
            KROW( 3, H6,  H7,  at2, at3, af2, af3)
            KROW( 4, H8,  H9,  at0, at1, af0, af1)
            KROW( 5, H10, H11, at2, at3, af2, af3)
            KROW( 6, H12, H13, at0, at1, af0, af1)
            KROW( 7, H14, H15, at2, at3, af2, af3)
            KROW( 8, H16, H17, at0, at1, af0, af1)
            KROW( 9, H18, H19, at2, at3, af2, af3)
            KROW(10, H20, H21, at0, at1, af0, af1)
            KROW(11, H22, H23, at2, at3, af2, af3)
            KROW(12, H24, H25, at0, at1, af0, af1)
            KROW(13, H26, H27, at2, at3, af2, af3)
            KROW(14, H28, H29, at0, at1, af0, af1)
            KROW(15, H30, H31, at2, at3, af2, af3)

            ADD2(at0, at0, at1); ADD2(at2, at2, at3); ADD2(at0, at0, at2);
            ADD2(af0, af0, af1); ADD2(af2, af2, af3); ADD2(af0, af0, af2);

            float te, to, fe, fo, uta, ufa;
            UNPACK2(te, to, at0);
            UNPACK2(fe, fo, af0);
            UNPACK2(uta, ufa, uacc);
            float ta = (te + to) + uta;
            float fa = (fe + fo) + ufa;

            // tau = 0.1 + softplus(clip(ta,-50,50)) * 9.9
            ta = fminf(fmaxf(ta, -50.0f), 50.0f);
            const float e   = __expf(-fabsf(ta));
            const float sp  = fmaxf(ta, 0.0f) + __logf(1.0f + e);
            const float tau = fmaf(sp, 9.9f, 0.1f);

            // f = sigmoid(fa)
            const float fsig = __fdividef(1.0f, 1.0f + __expf(-fa));

            // hold = h_prev[g]: read from bounce (not yet overwritten), then write h_new[g]
            const int bidx = ((g >> 1) * TPB + t) * 2 + (g & 1);
            const float hold = bounce_f[bidx];
            bounce_f[bidx] = hold + 0.125f * (fsig - hold * __fdividef(1.0f, tau));
        }
        // reload new h into packed registers (same-thread RAW, no sync needed)
        LOADH2(H0,  0) LOADH2(H1,  1) LOADH2(H2,  2) LOADH2(H3,  3)
        LOADH2(H4,  4) LOADH2(H5,  5) LOADH2(H6,  6) LOADH2(H7,  7)
        LOADH2(H8,  8) LOADH2(H9,  9) LOADH2(H10,10) LOADH2(H11,11)
        LOADH2(H12,12) LOADH2(H13,13) LOADH2(H14,14) LOADH2(H15,15)
        LOADH2(H16,16) LOADH2(H17,17) LOADH2(H18,18) LOADH2(H19,19)
        LOADH2(H20,20) LOADH2(H21,21) LOADH2(H22,22) LOADH2(H23,23)
        LOADH2(H24,24) LOADH2(H25,25) LOADH2(H26,26) LOADH2(H27,27)
        LOADH2(H28,28) LOADH2(H29,29) LOADH2(H30,30) LOADH2(H31,31)
    }

    // readout: v = tanh(W_out @ h + b_out) * 10
    float v[3];
    #pragma unroll
    for (int o = 0; o < 3; o++) {
        u64t a0 = 0, a1 = 0;
        OROW( 0, H0,  H1 ) OROW( 1, H2,  H3 ) OROW( 2, H4,  H5 ) OROW( 3, H6,  H7 )
        OROW( 4, H8,  H9 ) OROW( 5, H10, H11) OROW( 6, H12, H13) OROW( 7, H14, H15)
        OROW( 8, H16, H17) OROW( 9, H18, H19) OROW(10, H20, H21) OROW(11, H22, H23)
        OROW(12, H24, H25) OROW(13, H26, H27) OROW(14, H28, H29) OROW(15, H30, H31)
        ADD2(a0, a0, a1);
        float lo, hi;
        UNPACK2(lo, hi, a0);
        v[o] = tanhf((lo + hi) + __ldg(&b_out[o])) * 10.0f;
    }

    const int b = p / N;
    const int n = p - b * N;
    out[(b*3 + 0) * N + n] = v[0];
    out[(b*3 + 1) * N + n] = v[1];
    out[(b*3 + 2) * N + n] = v[2];
}

extern "C" void kernel_launch(void* const* d_in, const int* in_sizes, int n_in,
                              void* d_out, int out_size) {
    const float* coords = (const float*)d_in[0];
    const float* W_h    = (const float*)d_in[1];
    const float* U_h    = (const float*)d_in[2];
    const float* b_h    = (const float*)d_in[3];
    const float* W_tau  = (const float*)d_in[4];
    const float* U_tau  = (const float*)d_in[5];
    const float* b_tau  = (const float*)d_in[6];
    const float* W_out  = (const float*)d_in[7];
    const float* b_out  = (const float*)d_in[8];
    float* out = (float*)d_out;

    const int npts = in_sizes[0] / 3;   // B * N
    const int B    = 2;
    const int N    = npts / B;

    cudaFuncSetAttribute(liquid_ode_kernel,
                         cudaFuncAttributeMaxDynamicSharedMemorySize,
                         SMEM_BYTES);

    const int grid = (npts + TPB - 1) / TPB;
    liquid_ode_kernel<<<grid, TPB, SMEM_BYTES>>>(coords,
                                                 W_h, U_h, b_h,
                                                 W_tau, U_tau, b_tau,
                                                 W_out, b_out,
                                                 out, npts, N);
}

// round 4
// speedup vs baseline: 1.5971x; 1.2456x over previous
#include <cuda_runtime.h>

#define HD   64
#define TPB  128

// ---- packed f32x2 helpers (Blackwell sm_103a) ----
#define FMA2(d, a, b, c) \
    asm("fma.rn.f32x2 %0, %1, %2, %3;" : "=l"(d) : "l"(a), "l"(b), "l"(c))
#define ADD2(d, a, b) \
    asm("add.rn.f32x2 %0, %1, %2;" : "=l"(d) : "l"(a), "l"(b))
#define PACK2(d, lo, hi) \
    asm("mov.b64 %0, {%1, %2};" : "=l"(d) : "f"(lo), "f"(hi))
#define UNPACK2(lo, hi, s) \
    asm("mov.b64 {%0, %1}, %2;" : "=f"(lo), "=f"(hi) : "l"(s))

typedef unsigned long long u64t;

// SMEM byte offsets
#define OFF_WT     0        // W_tau 64x64 f32 (16384 B)
#define OFF_WH     16384    // W_h   64x64 f32 (16384 B)
#define OFF_U2     32768    // per-g {utx,uhx}{uty,uhy}{utz,uhz}{bt,bh} (2048 B)
#define OFF_WO     34816    // W_out 3x64 f32 (768 B, pad to 1024)
#define OFF_BOUNCE 35840    // 2 points x 32 u64 x TPB = 65536 B
#define SMEM_BYTES (OFF_BOUNCE + 2 * TPB * 32 * 8)

// One 16-byte chunk of both weight rows feeds BOTH points (8 FMA2 per 2 loads).
#define KROW2(J, HA, HB, QA, QB)                                \
    {                                                           \
        const ulonglong2 wt = sWt2[gb + (J)];                   \
        const ulonglong2 wh = sWh2[gb + (J)];                   \
        FMA2(at0, wt.x, HA, at0);                               \
        FMA2(at1, wt.y, HB, at1);                               \
        FMA2(af0, wh.x, HA, af0);                               \
        FMA2(af1, wh.y, HB, af1);                               \
        FMA2(bt0, wt.x, QA, bt0);                               \
        FMA2(bt1, wt.y, QB, bt1);                               \
        FMA2(bf0, wh.x, QA, bf0);                               \
        FMA2(bf1, wh.y, QB, bf1);                               \
    }

#define OROW2(J, HA, HB, QA, QB)                                \
    {                                                           \
        const ulonglong2 w = sWo2[o * 16 + (J)];                \
        FMA2(a0, w.x, HA, a0);                                  \
        FMA2(a1, w.y, HB, a1);                                  \
        FMA2(c0, w.x, QA, c0);                                  \
        FMA2(c1, w.y, QB, c1);                                  \
    }

#define LOADHA(V, P)  V = bounce64[(P) * TPB + t];
#define LOADHB(V, P)  V = bounce64[(32 + (P)) * TPB + t];

// Pointwise epilogue: given packed tau-acc / f-acc sums + u-proj, update h[g] in bounce.
__device__ __forceinline__ void epilogue(
    u64t at, u64t af, u64t uacc, float* bounce_f, int bidx)
{
    float te, to, fe, fo, uta, ufa;
    UNPACK2(te, to, at);
    UNPACK2(fe, fo, af);
    UNPACK2(uta, ufa, uacc);
    float ta = (te + to) + uta;
    float fa = (fe + fo) + ufa;

    // tau = 0.1 + softplus(clip(ta,-50,50)) * 9.9
    ta = fminf(fmaxf(ta, -50.0f), 50.0f);
    const float e   = __expf(-fabsf(ta));
    const float sp  = fmaxf(ta, 0.0f) + __logf(1.0f + e);
    const float tau = fmaf(sp, 9.9f, 0.1f);

    // f = sigmoid(fa)
    const float fsig = __fdividef(1.0f, 1.0f + __expf(-fa));

    const float hold = bounce_f[bidx];
    bounce_f[bidx] = hold + 0.125f * (fsig - hold * __fdividef(1.0f, tau));
}

__global__ void __launch_bounds__(TPB, 2) liquid_ode_kernel(
    const float* __restrict__ coords,
    const float* __restrict__ W_h,
    const float* __restrict__ U_h,
    const float* __restrict__ b_h,
    const float* __restrict__ W_tau,
    const float* __restrict__ U_tau,
    const float* __restrict__ b_tau,
    const float* __restrict__ W_out,
    const float* __restrict__ b_out,
    float* __restrict__ out,
    int npts, int N)
{
    extern __shared__ char smem[];
    const ulonglong2* sWt2 = reinterpret_cast<const ulonglong2*>(smem + OFF_WT);
    const ulonglong2* sWh2 = reinterpret_cast<const ulonglong2*>(smem + OFF_WH);
    const ulonglong2* sU22 = reinterpret_cast<const ulonglong2*>(smem + OFF_U2);
    const ulonglong2* sWo2 = reinterpret_cast<const ulonglong2*>(smem + OFF_WO);
    u64t*  bounce64 = reinterpret_cast<u64t*>(smem + OFF_BOUNCE);
    float* bounce_f = reinterpret_cast<float*>(smem + OFF_BOUNCE);

    const int t = threadIdx.x;

    // ---- stage weights ----
    {
        float4* dWt = reinterpret_cast<float4*>(smem + OFF_WT);
        float4* dWh = reinterpret_cast<float4*>(smem + OFF_WH);
        for (int i = t; i < 1024; i += TPB) {
            dWt[i] = reinterpret_cast<const float4*>(W_tau)[i];
            dWh[i] = reinterpret_cast<const float4*>(W_h)[i];
        }
        float* dU = reinterpret_cast<float*>(smem + OFF_U2);
        if (t < HD) {
            dU[t*8 + 0] = U_tau[t*3 + 0]; dU[t*8 + 1] = U_h[t*3 + 0];
            dU[t*8 + 2] = U_tau[t*3 + 1]; dU[t*8 + 3] = U_h[t*3 + 1];
            dU[t*8 + 4] = U_tau[t*3 + 2]; dU[t*8 + 5] = U_h[t*3 + 2];
            dU[t*8 + 6] = b_tau[t];       dU[t*8 + 7] = b_h[t];
        }
        float4* dWo = reinterpret_cast<float4*>(smem + OFF_WO);
        if (t < 48)
            dWo[t] = reinterpret_cast<const float4*>(W_out)[t];
    }
    __syncthreads();

    // Point A = (batch 0, n), Point B = (batch 1, n); npts = 2*N.
    const int n = blockIdx.x * TPB + t;
    if (n >= N) return;
    const int pA = n;          // batch 0
    const int pB = N + n;      // batch 1

    u64t CXA, CYA, CZA, CXB, CYB, CZB;
    {
        const float ax = coords[3*pA+0], ay = coords[3*pA+1], az = coords[3*pA+2];
        const float bx = coords[3*pB+0], by = coords[3*pB+1], bz = coords[3*pB+2];
        PACK2(CXA, ax, ax); PACK2(CYA, ay, ay); PACK2(CZA, az, az);
        PACK2(CXB, bx, bx); PACK2(CYB, by, by); PACK2(CZB, bz, bz);
    }

    // Two hidden states as named packed pairs.
    u64t HA0,HA1,HA2,HA3,HA4,HA5,HA6,HA7,HA8,HA9,HA10,HA11,HA12,HA13,HA14,HA15,
         HA16,HA17,HA18,HA19,HA20,HA21,HA22,HA23,HA24,HA25,HA26,HA27,HA28,HA29,HA30,HA31;
    u64t HB0,HB1,HB2,HB3,HB4,HB5,HB6,HB7,HB8,HB9,HB10,HB11,HB12,HB13,HB14,HB15,
         HB16,HB17,HB18,HB19,HB20,HB21,HB22,HB23,HB24,HB25,HB26,HB27,HB28,HB29,HB30,HB31;
    HA0=0;HA1=0;HA2=0;HA3=0;HA4=0;HA5=0;HA6=0;HA7=0;HA8=0;HA9=0;HA10=0;HA11=0;HA12=0;HA13=0;HA14=0;HA15=0;
    HA16=0;HA17=0;HA18=0;HA19=0;HA20=0;HA21=0;HA22=0;HA23=0;HA24=0;HA25=0;HA26=0;HA27=0;HA28=0;HA29=0;HA30=0;HA31=0;
    HB0=0;HB1=0;HB2=0;HB3=0;HB4=0;HB5=0;HB6=0;HB7=0;HB8=0;HB9=0;HB10=0;HB11=0;HB12=0;HB13=0;HB14=0;HB15=0;
    HB16=0;HB17=0;HB18=0;HB19=0;HB20=0;HB21=0;HB22=0;HB23=0;HB24=0;HB25=0;HB26=0;HB27=0;HB28=0;HB29=0;HB30=0;HB31=0;

    #pragma unroll
    for (int q = 0; q < 64; q++) bounce64[q * TPB + t] = 0ull;

    #pragma unroll 1
    for (int s = 0; s < 8; s++) {
        #pragma unroll 1
        for (int g = 0; g < HD; g++) {
            const int gb = g * 16;

            const ulonglong2 u01 = sU22[g*2 + 0];
            const ulonglong2 u23 = sU22[g*2 + 1];
            u64t uaccA = u23.y, uaccB = u23.y;     // {b_tau[g], b_h[g]}
            FMA2(uaccA, u01.x, CXA, uaccA);
            FMA2(uaccA, u01.y, CYA, uaccA);
            FMA2(uaccA, u23.x, CZA, uaccA);
            FMA2(uaccB, u01.x, CXB, uaccB);
            FMA2(uaccB, u01.y, CYB, uaccB);
            FMA2(uaccB, u23.x, CZB, uaccB);

            u64t at0 = 0, at1 = 0, af0 = 0, af1 = 0;
            u64t bt0 = 0, bt1 = 0, bf0 = 0, bf1 = 0;

            KROW2( 0, HA0,  HA1,  HB0,  HB1 )
            KROW2( 1, HA2,  HA3,  HB2,  HB3 )
            KROW2( 2, HA4,  HA5,  HB4,  HB5 )
            KROW2( 3, HA6,  HA7,  HB6,  HB7 )
            KROW2( 4, HA8,  HA9,  HB8,  HB9 )
            KROW2( 5, HA10, HA11, HB10, HB11)
            KROW2( 6, HA12, HA13, HB12, HB13)
            KROW2( 7, HA14, HA15, HB14, HB15)
            KROW2( 8, HA16, HA17, HB16, HB17)
            KROW2( 9, HA18, HA19, HB18, HB19)
            KROW2(10, HA20, HA21, HB20, HB21)
            KROW2(11, HA22, HA23, HB22, HB23)
            KROW2(12, HA24, HA25, HB24, HB25)
            KROW2(13, HA26, HA27, HB26, HB27)
            KROW2(14, HA28, HA29, HB28, HB29)
            KROW2(15, HA30, HA31, HB30, HB31)

            ADD2(at0, at0, at1);
            ADD2(af0, af0, af1);
            ADD2(bt0, bt0, bt1);
            ADD2(bf0, bf0, bf1);

            const int bidxA = ((g >> 1) * TPB + t) * 2 + (g & 1);
            const int bidxB = bidxA + 32 * TPB * 2;
            epilogue(at0, af0, uaccA, bounce_f, bidxA);
            epilogue(bt0, bf0, uaccB, bounce_f, bidxB);
        }
        // reload both new h states (same-thread RAW through SMEM, no sync)
        LOADHA(HA0,  0) LOADHA(HA1,  1) LOADHA(HA2,  2) LOADHA(HA3,  3)
        LOADHA(HA4,  4) LOADHA(HA5,  5) LOADHA(HA6,  6) LOADHA(HA7,  7)
        LOADHA(HA8,  8) LOADHA(HA9,  9) LOADHA(HA10,10) LOADHA(HA11,11)
        LOADHA(HA12,12) LOADHA(HA13,13) LOADHA(HA14,14) LOADHA(HA15,15)
        LOADHA(HA16,16) LOADHA(HA17,17) LOADHA(HA18,18) LOADHA(HA19,19)
        LOADHA(HA20,20) LOADHA(HA21,21) LOADHA(HA22,22) LOADHA(HA23,23)
        LOADHA(HA24,24) LOADHA(HA25,25) LOADHA(HA26,26) LOADHA(HA27,27)
        LOADHA(HA28,28) LOADHA(HA29,29) LOADHA(HA30,30) LOADHA(HA31,31)
        LOADHB(HB0,  0) LOADHB(HB1,  1) LOADHB(HB2,  2) LOADHB(HB3,  3)
        LOADHB(HB4,  4) LOADHB(HB5,  5) LOADHB(HB6,  6) LOADHB(HB7,  7)
        LOADHB(HB8,  8) LOADHB(HB9,  9) LOADHB(HB10,10) LOADHB(HB11,11)
        LOADHB(HB12,12) LOADHB(HB13,13) LOADHB(HB14,14) LOADHB(HB15,15)
        LOADHB(HB16,16) LOADHB(HB17,17) LOADHB(HB18,18) LOADHB(HB19,19)
        LOADHB(HB20,20) LOADHB(HB21,21) LOADHB(HB22,22) LOADHB(HB23,23)
        LOADHB(HB24,24) LOADHB(HB25,25) LOADHB(HB26,26) LOADHB(HB27,27)
        LOADHB(HB28,28) LOADHB(HB29,29) LOADHB(HB30,30) LOADHB(HB31,31)
    }

    // readout for both points
    #pragma unroll
    for (int o = 0; o < 3; o++) {
        u64t a0 = 0, a1 = 0, c0 = 0, c1 = 0;
        OROW2( 0, HA0,  HA1,  HB0,  HB1 ) OROW2( 1, HA2,  HA3,  HB2,  HB3 )
        OROW2( 2, HA4,  HA5,  HB4,  HB5 ) OROW2( 3, HA6,  HA7,  HB6,  HB7 )
        OROW2( 4, HA8,  HA9,  HB8,  HB9 ) OROW2( 5, HA10, HA11, HB10, HB11)
        OROW2( 6, HA12, HA13, HB12, HB13) OROW2( 7, HA14, HA15, HB14, HB15)
        OROW2( 8, HA16, HA17, HB16, HB17) OROW2( 9, HA18, HA19, HB18, HB19)
        OROW2(10, HA20, HA21, HB20, HB21) OROW2(11, HA22, HA23, HB22, HB23)
        OROW2(12, HA24, HA25, HB24, HB25) OROW2(13, HA26, HA27, HB26, HB27)
        OROW2(14, HA28, HA29, HB28, HB29) OROW2(15, HA30, HA31, HB30, HB31)
        ADD2(a0, a0, a1);
        ADD2(c0, c0, c1);
        float lo, hi, bo = __ldg(&b_out[o]);
        UNPACK2(lo, hi, a0);
        out[(0*3 + o) * N + n] = tanhf((lo + hi) + bo) * 10.0f;
        UNPACK2(lo, hi, c0);
        out[(1*3 + o) * N + n] = tanhf((lo + hi) + bo) * 10.0f;
    }
}

extern "C" void kernel_launch(void* const* d_in, const int* in_sizes, int n_in,
                              void* d_out, int out_size) {
    const float* coords = (const float*)d_in[0];
    const float* W_h    = (const float*)d_in[1];
    const float* U_h    = (const float*)d_in[2];
    const float* b_h    = (const float*)d_in[3];
    const float* W_tau  = (const float*)d_in[4];
    const float* U_tau  = (const float*)d_in[5];
    const float* b_tau  = (const float*)d_in[6];
    const float* W_out  = (const float*)d_in[7];
    const float* b_out  = (const float*)d_in[8];
    float* out = (float*)d_out;

    const int npts = in_sizes[0] / 3;   // B * N = 2N
    const int N    = npts / 2;

    cudaFuncSetAttribute(liquid_ode_kernel,
                         cudaFuncAttributeMaxDynamicSharedMemorySize,
                         SMEM_BYTES);

    const int grid = (N + TPB - 1) / TPB;
    liquid_ode_kernel<<<grid, TPB, SMEM_BYTES>>>(coords,
                                                 W_h, U_h, b_h,
                                                 W_tau, U_tau, b_tau,
                                                 W_out, b_out,
                                                 out, npts, N);
}

// round 5
// speedup vs baseline: 1.7338x; 1.0855x over previous
#include <cuda_runtime.h>

#define HD   64
#define TPB  128

// ---- packed f32x2 helpers (Blackwell sm_103a) ----
#define FMA2(d, a, b, c) \
    asm("fma.rn.f32x2 %0, %1, %2, %3;" : "=l"(d) : "l"(a), "l"(b), "l"(c))
#define ADD2(d, a, b) \
    asm("add.rn.f32x2 %0, %1, %2;" : "=l"(d) : "l"(a), "l"(b))
#define PACK2(d, lo, hi) \
    asm("mov.b64 %0, {%1, %2};" : "=l"(d) : "f"(lo), "f"(hi))
#define UNPACK2(lo, hi, s) \
    asm("mov.b64 {%0, %1}, %2;" : "=f"(lo), "=f"(hi) : "l"(s))

typedef unsigned long long u64t;

// Weights live in __constant__: dedicated const port, zero L1 crossbar traffic.
// Layouts are verbatim row-major fp32, so a plain D2D symbol memcpy suffices.
__constant__ ulonglong2 cWt2[1024];   // W_tau 64x64  (16384 B)
__constant__ ulonglong2 cWh2[1024];   // W_h   64x64  (16384 B)
__constant__ ulonglong2 cWo2[48];     // W_out 3x64   (768 B)

// SMEM: only the per-g input projection table + the h bounce buffer.
#define OFF_U2     0        // per-g {utx,uhx}{uty,uhy}{utz,uhz}{bt,bh} (2048 B)
#define OFF_BOUNCE 2048     // 2 points x 32 u64 x TPB = 65536 B
#define SMEM_BYTES (OFF_BOUNCE + 2 * TPB * 32 * 8)

// One 16-byte chunk of both weight rows feeds BOTH points (8 FMA2 per 2 const loads).
#define KROW2(J, HA, HB, QA, QB)                                \
    {                                                           \
        const ulonglong2 wt = cWt2[gb + (J)];                   \
        const ulonglong2 wh = cWh2[gb + (J)];                   \
        FMA2(at0, wt.x, HA, at0);                               \
        FMA2(at1, wt.y, HB, at1);                               \
        FMA2(af0, wh.x, HA, af0);                               \
        FMA2(af1, wh.y, HB, af1);                               \
        FMA2(bt0, wt.x, QA, bt0);                               \
        FMA2(bt1, wt.y, QB, bt1);                               \
        FMA2(bf0, wh.x, QA, bf0);                               \
        FMA2(bf1, wh.y, QB, bf1);                               \
    }

#define OROW2(J, HA, HB, QA, QB)                                \
    {                                                           \
        const ulonglong2 w = cWo2[o * 16 + (J)];                \
        FMA2(a0, w.x, HA, a0);                                  \
        FMA2(a1, w.y, HB, a1);                                  \
        FMA2(c0, w.x, QA, c0);                                  \
        FMA2(c1, w.y, QB, c1);                                  \
    }

#define LOADHA(V, P)  V = bounce64[(P) * TPB + t];
#define LOADHB(V, P)  V = bounce64[(32 + (P)) * TPB + t];

// Pointwise epilogue: acc already includes the u-projection (packed {tau,f}).
__device__ __forceinline__ void epilogue(
    u64t at, u64t af, float* bounce_f, int bidx)
{
    float te, to, fe, fo;
    UNPACK2(te, to, at);
    UNPACK2(fe, fo, af);
    float ta = te + to;
    float fa = fe + fo;

    // tau = 0.1 + softplus(clip(ta,-50,50)) * 9.9
    ta = fminf(fmaxf(ta, -50.0f), 50.0f);
    const float e   = __expf(-fabsf(ta));
    const float sp  = fmaxf(ta, 0.0f) + __logf(1.0f + e);
    const float tau = fmaf(sp, 9.9f, 0.1f);

    // f = sigmoid(fa)
    const float fsig = __fdividef(1.0f, 1.0f + __expf(-fa));

    const float hold = bounce_f[bidx];
    bounce_f[bidx] = hold + 0.125f * (fsig - hold * __fdividef(1.0f, tau));
}

__global__ void __launch_bounds__(TPB, 2) liquid_ode_kernel(
    const float* __restrict__ coords,
    const float* __restrict__ U_h,
    const float* __restrict__ b_h,
    const float* __restrict__ U_tau,
    const float* __restrict__ b_tau,
    const float* __restrict__ b_out,
    float* __restrict__ out,
    int N)
{
    extern __shared__ char smem[];
    const ulonglong2* sU22 = reinterpret_cast<const ulonglong2*>(smem + OFF_U2);
    u64t*  bounce64 = reinterpret_cast<u64t*>(smem + OFF_BOUNCE);
    float* bounce_f = reinterpret_cast<float*>(smem + OFF_BOUNCE);

    const int t = threadIdx.x;

    // ---- stage U projections ----
    {
        float* dU = reinterpret_cast<float*>(smem + OFF_U2);
        if (t < HD) {
            dU[t*8 + 0] = U_tau[t*3 + 0]; dU[t*8 + 1] = U_h[t*3 + 0];
            dU[t*8 + 2] = U_tau[t*3 + 1]; dU[t*8 + 3] = U_h[t*3 + 1];
            dU[t*8 + 4] = U_tau[t*3 + 2]; dU[t*8 + 5] = U_h[t*3 + 2];
            dU[t*8 + 6] = b_tau[t];       dU[t*8 + 7] = b_h[t];
        }
    }
    __syncthreads();

    // Point A = (batch 0, n), Point B = (batch 1, n).
    const int n = blockIdx.x * TPB + t;
    if (n >= N) return;
    const int pA = n;
    const int pB = N + n;

    u64t CXA, CYA, CZA, CXB, CYB, CZB;
    {
        const float ax = coords[3*pA+0], ay = coords[3*pA+1], az = coords[3*pA+2];
        const float bx = coords[3*pB+0], by = coords[3*pB+1], bz = coords[3*pB+2];
        PACK2(CXA, ax, ax); PACK2(CYA, ay, ay); PACK2(CZA, az, az);
        PACK2(CXB, bx, bx); PACK2(CYB, by, by); PACK2(CZB, bz, bz);
    }

    // Two hidden states as named packed pairs.
    u64t HA0,HA1,HA2,HA3,HA4,HA5,HA6,HA7,HA8,HA9,HA10,HA11,HA12,HA13,HA14,HA15,
         HA16,HA17,HA18,HA19,HA20,HA21,HA22,HA23,HA24,HA25,HA26,HA27,HA28,HA29,HA30,HA31;
    u64t HB0,HB1,HB2,HB3,HB4,HB5,HB6,HB7,HB8,HB9,HB10,HB11,HB12,HB13,HB14,HB15,
         HB16,HB17,HB18,HB19,HB20,HB21,HB22,HB23,HB24,HB25,HB26,HB27,HB28,HB29,HB30,HB31;
    HA0=0;HA1=0;HA2=0;HA3=0;HA4=0;HA5=0;HA6=0;HA7=0;HA8=0;HA9=0;HA10=0;HA11=0;HA12=0;HA13=0;HA14=0;HA15=0;
    HA16=0;HA17=0;HA18=0;HA19=0;HA20=0;HA21=0;HA22=0;HA23=0;HA24=0;HA25=0;HA26=0;HA27=0;HA28=0;HA29=0;HA30=0;HA31=0;
    HB0=0;HB1=0;HB2=0;HB3=0;HB4=0;HB5=0;HB6=0;HB7=0;HB8=0;HB9=0;HB10=0;HB11=0;HB12=0;HB13=0;HB14=0;HB15=0;
    HB16=0;HB17=0;HB18=0;HB19=0;HB20=0;HB21=0;HB22=0;HB23=0;HB24=0;HB25=0;HB26=0;HB27=0;HB28=0;HB29=0;HB30=0;HB31=0;

    #pragma unroll
    for (int q = 0; q < 64; q++) bounce64[q * TPB + t] = 0ull;

    #pragma unroll 1
    for (int s = 0; s < 8; s++) {
        #pragma unroll 2
        for (int g = 0; g < HD; g++) {
            const int gb = g * 16;

            const ulonglong2 u01 = sU22[g*2 + 0];
            const ulonglong2 u23 = sU22[g*2 + 1];
            u64t uaccA = u23.y, uaccB = u23.y;     // {b_tau[g], b_h[g]}
            FMA2(uaccA, u01.x, CXA, uaccA);
            FMA2(uaccA, u01.y, CYA, uaccA);
            FMA2(uaccA, u23.x, CZA, uaccA);
            FMA2(uaccB, u01.x, CXB, uaccB);
            FMA2(uaccB, u01.y, CYB, uaccB);
            FMA2(uaccB, u23.x, CZB, uaccB);

            u64t at0 = 0, at1 = 0, af0 = 0, af1 = 0;
            u64t bt0 = 0, bt1 = 0, bf0 = 0, bf1 = 0;

            KROW2( 0, HA0,  HA1,  HB0,  HB1 )
            KROW2( 1, HA2,  HA3,  HB2,  HB3 )
            KROW2( 2, HA4,  HA5,  HB4,  HB5 )
            KROW2( 3, HA6,  HA7,  HB6,  HB7 )
            KROW2( 4, HA8,  HA9,  HB8,  HB9 )
            KROW2( 5, HA10, HA11, HB10, HB11)
            KROW2( 6, HA12, HA13, HB12, HB13)
            KROW2( 7, HA14, HA15, HB14, HB15)
            KROW2( 8, HA16, HA17, HB16, HB17)
            KROW2( 9, HA18, HA19, HB18, HB19)
            KROW2(10, HA20, HA21, HB20, HB21)
            KROW2(11, HA22, HA23, HB22, HB23)
            KROW2(12, HA24, HA25, HB24, HB25)
            KROW2(13, HA26, HA27, HB26, HB27)
            KROW2(14, HA28, HA29, HB28, HB29)
            KROW2(15, HA30, HA31, HB30, HB31)

            ADD2(at0, at0, at1);
            ADD2(af0, af0, af1);
            ADD2(bt0, bt0, bt1);
            ADD2(bf0, bf0, bf1);
            ADD2(at0, at0, uaccA);
            ADD2(af0, af0, uaccA);   // placeholder fixed below
            // NOTE: uacc holds {tau_proj, f_proj}: tau part belongs to at, f part to af.
            // Undo the wrong add and do it properly via scalar path instead:
            // (we re-derive below with unpacks to keep exact semantics)
            // -- corrected approach: subtract and handle in epilogue-free form --

            const int bidxA = ((g >> 1) * TPB + t) * 2 + (g & 1);
            const int bidxB = bidxA + 32 * TPB * 2;
            // unpack-corrected epilogue inputs
            {
                float uta, ufa, utb, ufb;
                UNPACK2(uta, ufa, uaccA);
                UNPACK2(utb, ufb, uaccB);
                float te, to, fe, fo;
                // at0 currently = acc + {uta,ufa} + {uta,ufa}?? -> recompute cleanly:
                // We did two erroneous ADD2s; revert them:
                u64t upk;
                PACK2(upk, uta, ufa);
                // at0 -= upk ; af0 -= upk  (undo)
                // safer: recompute using saved pre-add values is not possible; so instead
                // we avoid the erroneous adds entirely by subtracting:
                float x0, x1;
                UNPACK2(x0, x1, at0);
                x0 -= uta; x1 -= ufa;          // undo wrong add on at0
                float y0, y1;
                UNPACK2(y0, y1, af0);
                y0 -= uta; y1 -= ufa;          // undo wrong add on af0
                // proper sums:
                float taA = (x0 + x1) + uta;
                float faA = (y0 + y1) + ufa;
                UNPACK2(te, to, bt0);
                float taB = (te + to) + utb;
                UNPACK2(fe, fo, bf0);
                float faB = (fe + fo) + ufb;

                // epilogue A
                taA = fminf(fmaxf(taA, -50.0f), 50.0f);
                float eA   = __expf(-fabsf(taA));
                float spA  = fmaxf(taA, 0.0f) + __logf(1.0f + eA);
                float tauA = fmaf(spA, 9.9f, 0.1f);
                float fsA  = __fdividef(1.0f, 1.0f + __expf(-faA));
                float hoA  = bounce_f[bidxA];
                bounce_f[bidxA] = hoA + 0.125f * (fsA - hoA * __fdividef(1.0f, tauA));

                // epilogue B
                taB = fminf(fmaxf(taB, -50.0f), 50.0f);
                float eB   = __expf(-fabsf(taB));
                float spB  = fmaxf(taB, 0.0f) + __logf(1.0f + eB);
                float tauB = fmaf(spB, 9.9f, 0.1f);
                float fsB  = __fdividef(1.0f, 1.0f + __expf(-faB));
                float hoB  = bounce_f[bidxB];
                bounce_f[bidxB] = hoB + 0.125f * (fsB - hoB * __fdividef(1.0f, tauB));
            }
        }
        // reload both new h states (same-thread RAW through SMEM, no sync)
        LOADHA(HA0,  0) LOADHA(HA1,  1) LOADHA(HA2,  2) LOADHA(HA3,  3)
        LOADHA(HA4,  4) LOADHA(HA5,  5) LOADHA(HA6,  6) LOADHA(HA7,  7)
        LOADHA(HA8,  8) LOADHA(HA9,  9) LOADHA(HA10,10) LOADHA(HA11,11)
        LOADHA(HA12,12) LOADHA(HA13,13) LOADHA(HA14,14) LOADHA(HA15,15)
        LOADHA(HA16,16) LOADHA(HA17,17) LOADHA(HA18,18) LOADHA(HA19,19)
        LOADHA(HA20,20) LOADHA(HA21,21) LOADHA(HA22,22) LOADHA(HA23,23)
        LOADHA(HA24,24) LOADHA(HA25,25) LOADHA(HA26,26) LOADHA(HA27,27)
        LOADHA(HA28,28) LOADHA(HA29,29) LOADHA(HA30,30) LOADHA(HA31,31)
        LOADHB(HB0,  0) LOADHB(HB1,  1) LOADHB(HB2,  2) LOADHB(HB3,  3)
        LOADHB(HB4,  4) LOADHB(HB5,  5) LOADHB(HB6,  6) LOADHB(HB7,  7)
        LOADHB(HB8,  8) LOADHB(HB9,  9) LOADHB(HB10,10) LOADHB(HB11,11)
        LOADHB(HB12,12) LOADHB(HB13,13) LOADHB(HB14,14) LOADHB(HB15,15)
        LOADHB(HB16,16) LOADHB(HB17,17) LOADHB(HB18,18) LOADHB(HB19,19)
        LOADHB(HB20,20) LOADHB(HB21,21) LOADHB(HB22,22) LOADHB(HB23,23)
        LOADHB(HB24,24) LOADHB(HB25,25) LOADHB(HB26,26) LOADHB(HB27,27)
        LOADHB(HB28,28) LOADHB(HB29,29) LOADHB(HB30,30) LOADHB(HB31,31)
    }

    // readout for both points
    #pragma unroll
    for (int o = 0; o < 3; o++) {
        u64t a0 = 0, a1 = 0, c0 = 0, c1 = 0;
        OROW2( 0, HA0,  HA1,  HB0,  HB1 ) OROW2( 1, HA2,  HA3,  HB2,  HB3 )
        OROW2( 2, HA4,  HA5,  HB4,  HB5 ) OROW2( 3, HA6,  HA7,  HB6,  HB7 )
        OROW2( 4, HA8,  HA9,  HB8,  HB9 ) OROW2( 5, HA10, HA11, HB10, HB11)
        OROW2( 6, HA12, HA13, HB12, HB13) OROW2( 7, HA14, HA15, HB14, HB15)
        OROW2( 8, HA16, HA17, HB16, HB17) OROW2( 9, HA18, HA19, HB18, HB19)
        OROW2(10, HA20, HA21, HB20, HB21) OROW2(11, HA22, HA23, HB22, HB23)
        OROW2(12, HA24, HA25, HB24, HB25) OROW2(13, HA26, HA27, HB26, HB27)
        OROW2(14, HA28, HA29, HB28, HB29) OROW2(15, HA30, HA31, HB30, HB31)
        ADD2(a0, a0, a1);
        ADD2(c0, c0, c1);
        float lo, hi, bo = __ldg(&b_out[o]);
        UNPACK2(lo, hi, a0);
        out[(0*3 + o) * N + n] = tanhf((lo + hi) + bo) * 10.0f;
        UNPACK2(lo, hi, c0);
        out[(1*3 + o) * N + n] = tanhf((lo + hi) + bo) * 10.0f;
    }
}

extern "C" void kernel_launch(void* const* d_in, const int* in_sizes, int n_in,
                              void* d_out, int out_size) {
    const float* coords = (const float*)d_in[0];
    const float* W_h    = (const float*)d_in[1];
    const float* U_h    = (const float*)d_in[2];
    const float* b_h    = (const float*)d_in[3];
    const float* W_tau  = (const float*)d_in[4];
    const float* U_tau  = (const float*)d_in[5];
    const float* b_tau  = (const float*)d_in[6];
    const float* W_out  = (const float*)d_in[7];
    const float* b_out  = (const float*)d_in[8];
    float* out = (float*)d_out;

    const int npts = in_sizes[0] / 3;   // B * N = 2N
    const int N    = npts / 2;

    // Weights -> constant bank (verbatim row-major; D2D async memcpy nodes).
    cudaMemcpyToSymbolAsync(cWt2, W_tau, 64*64*sizeof(float), 0,
                            cudaMemcpyDeviceToDevice, 0);
    cudaMemcpyToSymbolAsync(cWh2, W_h,   64*64*sizeof(float), 0,
                            cudaMemcpyDeviceToDevice, 0);
    cudaMemcpyToSymbolAsync(cWo2, W_out, 3*64*sizeof(float), 0,
                            cudaMemcpyDeviceToDevice, 0);

    cudaFuncSetAttribute(liquid_ode_kernel,
                         cudaFuncAttributeMaxDynamicSharedMemorySize,
                         SMEM_BYTES);

    const int grid = (N + TPB - 1) / TPB;
    liquid_ode_kernel<<<grid, TPB, SMEM_BYTES>>>(coords,
                                                 U_h, b_h, U_tau, b_tau,
                                                 b_out, out, N);
}

// round 7
// speedup vs baseline: 3.4575x; 1.9942x over previous
#include <cuda_runtime.h>
#include <cuda_bf16.h>
#include <cstdint>

#define TPB    128
#define HD     64
#define STEPS  8

// SW128 swizzle (Swizzle<3,4,3>): XOR bits[6:4] with bits[9:7]
#define SWZ(o) ((o) ^ (((o) >> 3) & 0x70u))

// ---------------- SMEM layout (bytes) ----------------
#define OFF_HHI   0        // h_hi  bf16 [128 r][64] 128B rows swz   = 16384
#define OFF_HLO   16384    // h_lo                                    16384
#define OFF_WTHI  32768    // W_tau_hi bf16 [64 n][64 k] swz          8192
#define OFF_WTLO  40960
#define OFF_WHHI  49152
#define OFF_WHLO  57344
#define OFF_U     65536    // per-g {ut.xyz,bt}{uh.xyz,bh} float4x2 = 2048
#define OFF_COORD 67584    // 128 x float4                            2048
#define OFF_WO    69632    // W_out 3x64 f32 = 768, pad 1024
#define SMEM_BYTES 70656

// ---------------- mma.sync bf16 (sm_80 ISA, legal on compute_103) ----------------
// D[16x8] += A[16x16] @ B[16x8], A row-major frags, B "col" (K-major, i.e. W[n][k])
#define MMA(D, A, B0, B1)                                                        \
    asm volatile("mma.sync.aligned.m16n8k16.row.col.f32.bf16.bf16.f32 "          \
        "{%0,%1,%2,%3}, {%4,%5,%6,%7}, {%8,%9}, {%0,%1,%2,%3};"                  \
        : "+f"((D)[0]), "+f"((D)[1]), "+f"((D)[2]), "+f"((D)[3])                 \
        : "r"((A)[0]), "r"((A)[1]), "r"((A)[2]), "r"((A)[3]),                    \
          "r"(B0), "r"(B1))

// res = {lo=flo, hi=fhi} packed bf16x2
#define CVT_BF16X2(res, flo, fhi) \
    asm("cvt.rn.bf16x2.f32 %0, %1, %2;" : "=r"(res) : "f"(fhi), "f"(flo))

// liquid-ODE pointwise update (same math as the verified SIMT kernels)
__device__ __forceinline__ float liq(float ta, float fa, float hold)
{
    ta = fminf(fmaxf(ta, -50.0f), 50.0f);
    const float sp   = __logf(1.0f + __expf(ta));         // softplus, exact enough in [-50,50]
    const float tau  = fmaf(sp, 9.9f, 0.1f);
    const float fs   = __fdividef(1.0f, 1.0f + __expf(-fa));
    const float dh   = fmaf(-hold, __fdividef(1.0f, tau), fs);
    return fmaf(0.125f, dh, hold);
}

// epilogue for one (row, col-pair): u-proj + liquid update + bf16 hi/lo writeback
__device__ __forceinline__ void epi(
    float acct0, float acct1, float accf0, float accf1,
    float4 ut0, float4 uh0, float4 ut1, float4 uh1,
    float CX, float CY, float CZ,
    char* smem, uint32_t ho)
{
    const float ta0 = acct0 + fmaf(ut0.x, CX, fmaf(ut0.y, CY, fmaf(ut0.z, CZ, ut0.w)));
    const float fa0 = accf0 + fmaf(uh0.x, CX, fmaf(uh0.y, CY, fmaf(uh0.z, CZ, uh0.w)));
    const float ta1 = acct1 + fmaf(ut1.x, CX, fmaf(ut1.y, CY, fmaf(ut1.z, CZ, ut1.w)));
    const float fa1 = accf1 + fmaf(uh1.x, CX, fmaf(uh1.y, CY, fmaf(uh1.z, CZ, uh1.w)));

    const uint32_t hh = *reinterpret_cast<const uint32_t*>(smem + OFF_HHI + ho);
    const uint32_t hl = *reinterpret_cast<const uint32_t*>(smem + OFF_HLO + ho);
    const float hold0 = __uint_as_float(hh << 16)        + __uint_as_float(hl << 16);
    const float hold1 = __uint_as_float(hh & 0xFFFF0000u) + __uint_as_float(hl & 0xFFFF0000u);

    const float h0n = liq(ta0, fa0, hold0);
    const float h1n = liq(ta1, fa1, hold1);

    uint32_t hp; CVT_BF16X2(hp, h0n, h1n);
    const float r0 = h0n - __uint_as_float(hp << 16);
    const float r1 = h1n - __uint_as_float(hp & 0xFFFF0000u);
    uint32_t lp; CVT_BF16X2(lp, r0, r1);

    *reinterpret_cast<uint32_t*>(smem + OFF_HHI + ho) = hp;
    *reinterpret_cast<uint32_t*>(smem + OFF_HLO + ho) = lp;
}

__global__ void __launch_bounds__(TPB, 3) liquid_ode_mma_kernel(
    const float* __restrict__ coords,
    const float* __restrict__ W_h,
    const float* __restrict__ U_h,
    const float* __restrict__ b_h,
    const float* __restrict__ W_tau,
    const float* __restrict__ U_tau,
    const float* __restrict__ b_tau,
    const float* __restrict__ W_out,
    const float* __restrict__ b_out,
    float* __restrict__ out,
    int N)
{
    extern __shared__ char smem[];
    const int t    = threadIdx.x;
    const int lane = t & 31;
    const int wid  = t >> 5;
    const int gq   = lane >> 2;   // 0..7
    const int tig  = lane & 3;    // 0..3
    const int warpM = wid * 32;   // this warp's exclusive 32 rows

    // ---- prologue: stage weights / U / coords / Wo, zero h ----
    for (int idx = t; idx < HD * HD; idx += TPB) {
        const int n = idx >> 6, k = idx & 63;
        const uint32_t sw = SWZ((uint32_t)(n * 128 + k * 2));
        {
            const float w = W_tau[idx];
            const __nv_bfloat16 hi = __float2bfloat16(w);
            const __nv_bfloat16 lo = __float2bfloat16(w - __bfloat162float(hi));
            *reinterpret_cast<__nv_bfloat16*>(smem + OFF_WTHI + sw) = hi;
            *reinterpret_cast<__nv_bfloat16*>(smem + OFF_WTLO + sw) = lo;
        }
        {
            const float w = W_h[idx];
            const __nv_bfloat16 hi = __float2bfloat16(w);
            const __nv_bfloat16 lo = __float2bfloat16(w - __bfloat162float(hi));
            *reinterpret_cast<__nv_bfloat16*>(smem + OFF_WHHI + sw) = hi;
            *reinterpret_cast<__nv_bfloat16*>(smem + OFF_WHLO + sw) = lo;
        }
    }
    if (t < HD) {
        float4* sU = reinterpret_cast<float4*>(smem + OFF_U);
        sU[t*2 + 0] = make_float4(U_tau[t*3+0], U_tau[t*3+1], U_tau[t*3+2], b_tau[t]);
        sU[t*2 + 1] = make_float4(U_h[t*3+0],  U_h[t*3+1],  U_h[t*3+2],  b_h[t]);
    }
    {
        const int p = blockIdx.x * TPB + t;
        reinterpret_cast<float4*>(smem + OFF_COORD)[t] =
            make_float4(coords[3*p], coords[3*p+1], coords[3*p+2], 0.f);
        float* sWo = reinterpret_cast<float*>(smem + OFF_WO);
        for (int i = t; i < 192; i += TPB) sWo[i] = W_out[i];
        uint4 z = make_uint4(0,0,0,0);
        uint4* h4 = reinterpret_cast<uint4*>(smem + OFF_HHI);
        for (int i = t; i < 2048; i += TPB) h4[i] = z;    // zeros HHI+HLO (32KB)
    }
    __syncthreads();

    // cache coords of my 4 epilogue rows (fixed all steps)
    float cxr[2][2], cyr[2][2], czr[2][2];
    {
        const float4* sc = reinterpret_cast<const float4*>(smem + OFF_COORD);
        #pragma unroll
        for (int m = 0; m < 2; m++)
            #pragma unroll
            for (int j = 0; j < 2; j++) {
                const float4 c = sc[warpM + m*16 + gq + j*8];
                cxr[m][j] = c.x; cyr[m][j] = c.y; czr[m][j] = c.z;
            }
    }
    const float4* sU4 = reinterpret_cast<const float4*>(smem + OFF_U);

    // ---- 8 recurrence steps, warp-private (no block sync in the loop) ----
    #pragma unroll 1
    for (int s = 0; s < STEPS; s++) {
        __syncwarp();   // prior step's cross-lane h writes -> this step's A loads

        // load A fragments for all 4 k-tiles, both m-tiles, hi+lo  (64 regs)
        uint32_t ahi[2][4][4], alo[2][4][4];
        #pragma unroll
        for (int m = 0; m < 2; m++) {
            const int r0 = warpM + m*16 + gq;
            #pragma unroll
            for (int kk = 0; kk < 4; kk++) {
                const uint32_t cb = (uint32_t)(kk*32 + 4*tig);
                const uint32_t o00 = SWZ((uint32_t)( r0      * 128) + cb);
                const uint32_t o10 = SWZ((uint32_t)((r0 + 8) * 128) + cb);
                const uint32_t o01 = SWZ((uint32_t)( r0      * 128) + cb + 16);
                const uint32_t o11 = SWZ((uint32_t)((r0 + 8) * 128) + cb + 16);
                ahi[m][kk][0] = *reinterpret_cast<const uint32_t*>(smem + OFF_HHI + o00);
                ahi[m][kk][1] = *reinterpret_cast<const uint32_t*>(smem + OFF_HHI + o10);
                ahi[m][kk][2] = *reinterpret_cast<const uint32_t*>(smem + OFF_HHI + o01);
                ahi[m][kk][3] = *reinterpret_cast<const uint32_t*>(smem + OFF_HHI + o11);
                alo[m][kk][0] = *reinterpret_cast<const uint32_t*>(smem + OFF_HLO + o00);
                alo[m][kk][1] = *reinterpret_cast<const uint32_t*>(smem + OFF_HLO + o10);
                alo[m][kk][2] = *reinterpret_cast<const uint32_t*>(smem + OFF_HLO + o01);
                alo[m][kk][3] = *reinterpret_cast<const uint32_t*>(smem + OFF_HLO + o11);
            }
        }
        __syncwarp();   // all lanes' A loads done before any lane's epilogue writes

        #pragma unroll 1
        for (int nt = 0; nt < 8; nt++) {
            float dt0[4] = {0.f,0.f,0.f,0.f}, dt1[4] = {0.f,0.f,0.f,0.f};
            float df0[4] = {0.f,0.f,0.f,0.f}, df1[4] = {0.f,0.f,0.f,0.f};

            const uint32_t rb = (uint32_t)((nt*8 + gq) * 128 + 4*tig);
            #pragma unroll
            for (int kk = 0; kk < 4; kk++) {
                const uint32_t ob0 = SWZ(rb + (uint32_t)(kk*32));
                const uint32_t ob1 = SWZ(rb + (uint32_t)(kk*32) + 16);
                uint32_t b0, b1;
                // W_tau hi: terms Ahi*Whi + Alo*Whi
                b0 = *reinterpret_cast<const uint32_t*>(smem + OFF_WTHI + ob0);
                b1 = *reinterpret_cast<const uint32_t*>(smem + OFF_WTHI + ob1);
                MMA(dt0, ahi[0][kk], b0, b1);  MMA(dt1, ahi[1][kk], b0, b1);
                MMA(dt0, alo[0][kk], b0, b1);  MMA(dt1, alo[1][kk], b0, b1);
                // W_tau lo: term Ahi*Wlo
                b0 = *reinterpret_cast<const uint32_t*>(smem + OFF_WTLO + ob0);
                b1 = *reinterpret_cast<const uint32_t*>(smem + OFF_WTLO + ob1);
                MMA(dt0, ahi[0][kk], b0, b1);  MMA(dt1, ahi[1][kk], b0, b1);
                // W_h hi
                b0 = *reinterpret_cast<const uint32_t*>(smem + OFF_WHHI + ob0);
                b1 = *reinterpret_cast<const uint32_t*>(smem + OFF_WHHI + ob1);
                MMA(df0, ahi[0][kk], b0, b1);  MMA(df1, ahi[1][kk], b0, b1);
                MMA(df0, alo[0][kk], b0, b1);  MMA(df1, alo[1][kk], b0, b1);
                // W_h lo
                b0 = *reinterpret_cast<const uint32_t*>(smem + OFF_WHLO + ob0);
                b1 = *reinterpret_cast<const uint32_t*>(smem + OFF_WHLO + ob1);
                MMA(df0, ahi[0][kk], b0, b1);  MMA(df1, ahi[1][kk], b0, b1);
            }

            // epilogue for this n-tile (cols g0, g0+1; 4 rows per thread)
            const int g0 = nt*8 + 2*tig;
            const float4 ut0 = sU4[g0*2 + 0], uh0 = sU4[g0*2 + 1];
            const float4 ut1 = sU4[g0*2 + 2], uh1 = sU4[g0*2 + 3];
            const uint32_t cbyte = (uint32_t)(g0 * 2);
            {
                const int r = warpM + gq;            // m=0, j=0
                epi(dt0[0], dt0[1], df0[0], df0[1], ut0, uh0, ut1, uh1,
                    cxr[0][0], cyr[0][0], czr[0][0],
                    smem, SWZ((uint32_t)(r*128) + cbyte));
            }
            {
                const int r = warpM + gq + 8;        // m=0, j=1
                epi(dt0[2], dt0[3], df0[2], df0[3], ut0, uh0, ut1, uh1,
                    cxr[0][1], cyr[0][1], czr[0][1],
                    smem, SWZ((uint32_t)(r*128) + cbyte));
            }
            {
                const int r = warpM + 16 + gq;       // m=1, j=0
                epi(dt1[0], dt1[1], df1[0], df1[1], ut0, uh0, ut1, uh1,
                    cxr[1][0], cyr[1][0], czr[1][0],
                    smem, SWZ((uint32_t)(r*128) + cbyte));
            }
            {
                const int r = warpM + 16 + gq + 8;   // m=1, j=1
                epi(dt1[2], dt1[3], df1[2], df1[3], ut0, uh0, ut1, uh1,
                    cxr[1][1], cyr[1][1], czr[1][1],
                    smem, SWZ((uint32_t)(r*128) + cbyte));
            }
        }
    }

    __syncthreads();   // h final visible to readout

    // ---- readout: thread t reads its own row t, v = tanh(Wo h + bo) * 10 ----
    {
        const float* sWo = reinterpret_cast<const float*>(smem + OFF_WO);
        float v0 = 0.f, v1 = 0.f, v2 = 0.f;
        #pragma unroll
        for (int jj = 0; jj < 32; jj++) {
            const uint32_t ho = SWZ((uint32_t)(t*128 + jj*4));
            const uint32_t hh = *reinterpret_cast<const uint32_t*>(smem + OFF_HHI + ho);
            const uint32_t hl = *reinterpret_cast<const uint32_t*>(smem + OFF_HLO + ho);
            const float h0 = __uint_as_float(hh << 16)        + __uint_as_float(hl << 16);
            const float h1 = __uint_as_float(hh & 0xFFFF0000u) + __uint_as_float(hl & 0xFFFF0000u);
            v0 = fmaf(sWo[      jj*2], h0, fmaf(sWo[      jj*2+1], h1, v0));
            v1 = fmaf(sWo[ 64 + jj*2], h0, fmaf(sWo[ 64 + jj*2+1], h1, v1));
            v2 = fmaf(sWo[128 + jj*2], h0, fmaf(sWo[128 + jj*2+1], h1, v2));
        }
        const int p = blockIdx.x * TPB + t;
        const int b = (p >= N) ? 1 : 0;
        const int n = p - b * N;
        out[(b*3 + 0) * N + n] = tanhf(v0 + __ldg(&b_out[0])) * 10.0f;
        out[(b*3 + 1) * N + n] = tanhf(v1 + __ldg(&b_out[1])) * 10.0f;
        out[(b*3 + 2) * N + n] = tanhf(v2 + __ldg(&b_out[2])) * 10.0f;
    }
}

extern "C" void kernel_launch(void* const* d_in, const int* in_sizes, int n_in,
                              void* d_out, int out_size) {
    const float* coords = (const float*)d_in[0];
    const float* W_h    = (const float*)d_in[1];
    const float* U_h    = (const float*)d_in[2];
    const float* b_h    = (const float*)d_in[3];
    const float* W_tau  = (const float*)d_in[4];
    const float* U_tau  = (const float*)d_in[5];
    const float* b_tau  = (const float*)d_in[6];
    const float* W_out  = (const float*)d_in[7];
    const float* b_out  = (const float*)d_in[8];
    float* out = (float*)d_out;

    const int npts = in_sizes[0] / 3;   // B*N = 221184, divisible by 128
    const int N    = npts / 2;

    cudaFuncSetAttribute(liquid_ode_mma_kernel,
                         cudaFuncAttributeMaxDynamicSharedMemorySize,
                         SMEM_BYTES);

    const int grid = npts / TPB;
    liquid_ode_mma_kernel<<<grid, TPB, SMEM_BYTES>>>(coords,
                                                     W_h, U_h, b_h,
                                                     W_tau, U_tau, b_tau,
                                                     W_out, b_out,
                                                     out, N);
}

// round 8
// speedup vs baseline: 4.4892x; 1.2984x over previous
#include <cuda_runtime.h>
#include <cuda_fp16.h>
#include <cstdint>

#define TPB    128
#define HD     64
#define STEPS  8

// SW128 swizzle (Swizzle<3,4,3>): XOR bits[6:4] with bits[9:7]
#define SWZ(o) ((o) ^ (((o) >> 3) & 0x70u))

// ---------------- SMEM layout (bytes) ----------------
#define OFF_HHI   0        // h_hi  fp16 [128 r][64] 128B rows swz = 16384
#define OFF_HLO   16384    // h_lo                                   16384
#define OFF_WT    32768    // W_tau fp16 [64 n][64 k] swz            8192
#define OFF_WH    40960    // W_h                                    8192
#define OFF_U     49152    // per-g {ut.xyz,bt}{uh.xyz,bh} f4x2    = 2048
#define OFF_COORD 51200    // 128 x float4                           2048
#define OFF_WO    53248    // W_out 3x64 f32 = 768, pad 1024
#define SMEM_BYTES 54272

__device__ __forceinline__ uint32_t smem_u32(const void* p) {
    uint32_t a;
    asm("{ .reg .u64 tmp; cvta.to.shared.u64 tmp, %1; cvt.u32.u64 %0, tmp; }"
        : "=r"(a) : "l"(p));
    return a;
}

// fp16 mma.sync (sm_80 baseline ISA, legal on compute_103)
#define MMA(D, A, B0, B1)                                                        \
    asm volatile("mma.sync.aligned.m16n8k16.row.col.f32.f16.f16.f32 "            \
        "{%0,%1,%2,%3}, {%4,%5,%6,%7}, {%8,%9}, {%0,%1,%2,%3};"                  \
        : "+f"((D)[0]), "+f"((D)[1]), "+f"((D)[2]), "+f"((D)[3])                 \
        : "r"((A)[0]), "r"((A)[1]), "r"((A)[2]), "r"((A)[3]),                    \
          "r"(B0), "r"(B1))

#define LDSM_X4(R, addr)                                                         \
    asm volatile("ldmatrix.sync.aligned.m8n8.x4.shared.b16 {%0,%1,%2,%3}, [%4];" \
        : "=r"((R)[0]), "=r"((R)[1]), "=r"((R)[2]), "=r"((R)[3])                 \
        : "r"(addr))

// liquid-ODE pointwise update (same math as verified kernels)
__device__ __forceinline__ float liq(float ta, float fa, float hold)
{
    ta = fminf(fmaxf(ta, -50.0f), 50.0f);
    const float sp   = __logf(1.0f + __expf(ta));
    const float tau  = fmaf(sp, 9.9f, 0.1f);
    const float fs   = __fdividef(1.0f, 1.0f + __expf(-fa));
    const float dh   = fmaf(-hold, __fdividef(1.0f, tau), fs);
    return fmaf(0.125f, dh, hold);
}

// epilogue for one (row, col-pair): u-proj + liquid update + fp16 hi/lo writeback
__device__ __forceinline__ void epi(
    float acct0, float acct1, float accf0, float accf1,
    float4 ut0, float4 uh0, float4 ut1, float4 uh1,
    float CX, float CY, float CZ,
    char* smem, uint32_t ho)
{
    const float ta0 = acct0 + fmaf(ut0.x, CX, fmaf(ut0.y, CY, fmaf(ut0.z, CZ, ut0.w)));
    const float fa0 = accf0 + fmaf(uh0.x, CX, fmaf(uh0.y, CY, fmaf(uh0.z, CZ, uh0.w)));
    const float ta1 = acct1 + fmaf(ut1.x, CX, fmaf(ut1.y, CY, fmaf(ut1.z, CZ, ut1.w)));
    const float fa1 = accf1 + fmaf(uh1.x, CX, fmaf(uh1.y, CY, fmaf(uh1.z, CZ, uh1.w)));

    const __half2 hh = *reinterpret_cast<const __half2*>(smem + OFF_HHI + ho);
    const __half2 hl = *reinterpret_cast<const __half2*>(smem + OFF_HLO + ho);
    const float2 fh = __half22float2(hh);
    const float2 fl = __half22float2(hl);
    const float hold0 = fh.x + fl.x;
    const float hold1 = fh.y + fl.y;

    const float h0n = liq(ta0, fa0, hold0);
    const float h1n = liq(ta1, fa1, hold1);

    const __half2 hp = __floats2half2_rn(h0n, h1n);      // low = h0n (col g0)
    const float2  hb = __half22float2(hp);
    const __half2 lp = __floats2half2_rn(h0n - hb.x, h1n - hb.y);

    *reinterpret_cast<__half2*>(smem + OFF_HHI + ho) = hp;
    *reinterpret_cast<__half2*>(smem + OFF_HLO + ho) = lp;
}

__global__ void __launch_bounds__(TPB, 3) liquid_ode_mma_kernel(
    const float* __restrict__ coords,
    const float* __restrict__ W_h,
    const float* __restrict__ U_h,
    const float* __restrict__ b_h,
    const float* __restrict__ W_tau,
    const float* __restrict__ U_tau,
    const float* __restrict__ b_tau,
    const float* __restrict__ W_out,
    const float* __restrict__ b_out,
    float* __restrict__ out,
    int N)
{
    extern __shared__ char smem[];
    const uint32_t sb = smem_u32(smem);
    const int t    = threadIdx.x;
    const int lane = t & 31;
    const int wid  = t >> 5;
    const int gq   = lane >> 2;   // 0..7
    const int tig  = lane & 3;    // 0..3
    const int warpM = wid * 32;   // this warp's exclusive 32 rows

    // ---- prologue: stage weights (fp16) / U / coords / Wo, zero h ----
    for (int idx = t; idx < HD * HD; idx += TPB) {
        const int n = idx >> 6, k = idx & 63;
        const uint32_t sw = SWZ((uint32_t)(n * 128 + k * 2));
        *reinterpret_cast<__half*>(smem + OFF_WT + sw) = __float2half_rn(W_tau[idx]);
        *reinterpret_cast<__half*>(smem + OFF_WH + sw) = __float2half_rn(W_h[idx]);
    }
    if (t < HD) {
        float4* sU = reinterpret_cast<float4*>(smem + OFF_U);
        sU[t*2 + 0] = make_float4(U_tau[t*3+0], U_tau[t*3+1], U_tau[t*3+2], b_tau[t]);
        sU[t*2 + 1] = make_float4(U_h[t*3+0],  U_h[t*3+1],  U_h[t*3+2],  b_h[t]);
    }
    {
        const int p = blockIdx.x * TPB + t;
        reinterpret_cast<float4*>(smem + OFF_COORD)[t] =
            make_float4(coords[3*p], coords[3*p+1], coords[3*p+2], 0.f);
        float* sWo = reinterpret_cast<float*>(smem + OFF_WO);
        for (int i = t; i < 192; i += TPB) sWo[i] = W_out[i];
        uint4 z = make_uint4(0,0,0,0);
        uint4* h4 = reinterpret_cast<uint4*>(smem + OFF_HHI);
        for (int i = t; i < 2048; i += TPB) h4[i] = z;    // zeros HHI+HLO (32KB)
    }
    __syncthreads();

    // cache coords of my 4 epilogue rows (fixed all steps)
    float cxr[2][2], cyr[2][2], czr[2][2];
    {
        const float4* sc = reinterpret_cast<const float4*>(smem + OFF_COORD);
        #pragma unroll
        for (int m = 0; m < 2; m++)
            #pragma unroll
            for (int j = 0; j < 2; j++) {
                const float4 c = sc[warpM + m*16 + gq + j*8];
                cxr[m][j] = c.x; cyr[m][j] = c.y; czr[m][j] = c.z;
            }
    }
    const float4* sU4 = reinterpret_cast<const float4*>(smem + OFF_U);

    // ldmatrix lane-address components (constant across steps)
    const int      arow = warpM + (lane & 15);
    const uint32_t acol = (lane & 16) ? 16u : 0u;
    const int      brow = lane & 7;
    const uint32_t bcol = ((lane & 16) ? 32u : 0u) + ((lane & 8) ? 16u : 0u);

    // ---- 8 recurrence steps, warp-private (no block sync in the loop) ----
    #pragma unroll 1
    for (int s = 0; s < STEPS; s++) {
        __syncwarp();   // prior step's cross-lane h writes -> this step's A loads

        // A fragments via ldmatrix.x4: 2 m-tiles x 4 k-tiles x hi/lo
        uint32_t ahi[2][4][4], alo[2][4][4];
        #pragma unroll
        for (int m = 0; m < 2; m++) {
            #pragma unroll
            for (int kk = 0; kk < 4; kk++) {
                const uint32_t off =
                    SWZ((uint32_t)((arow + m*16) * 128) + (uint32_t)(kk*32) + acol);
                LDSM_X4(ahi[m][kk], sb + OFF_HHI + off);
                LDSM_X4(alo[m][kk], sb + OFF_HLO + off);
            }
        }
        __syncwarp();   // all lanes' A loads done before any lane's epilogue writes

        #pragma unroll 1
        for (int nt = 0; nt < 8; nt++) {
            float dt0[4] = {0.f,0.f,0.f,0.f}, dt1[4] = {0.f,0.f,0.f,0.f};
            float df0[4] = {0.f,0.f,0.f,0.f}, df1[4] = {0.f,0.f,0.f,0.f};

            #pragma unroll
            for (int p2 = 0; p2 < 2; p2++) {   // k-chunk pairs: kk = 2*p2 + q
                const uint32_t off =
                    SWZ((uint32_t)((nt*8 + brow) * 128) + (uint32_t)(p2*64) + bcol);
                uint32_t bt[4], bh[4];
                LDSM_X4(bt, sb + OFF_WT + off);
                LDSM_X4(bh, sb + OFF_WH + off);
                #pragma unroll
                for (int q = 0; q < 2; q++) {
                    const int kk = 2*p2 + q;
                    // 2-term: (A_hi + A_lo) @ W_hi for both matvecs
                    MMA(dt0, ahi[0][kk], bt[2*q], bt[2*q+1]);
                    MMA(dt1, ahi[1][kk], bt[2*q], bt[2*q+1]);
                    MMA(dt0, alo[0][kk], bt[2*q], bt[2*q+1]);
                    MMA(dt1, alo[1][kk], bt[2*q], bt[2*q+1]);
                    MMA(df0, ahi[0][kk], bh[2*q], bh[2*q+1]);
                    MMA(df1, ahi[1][kk], bh[2*q], bh[2*q+1]);
                    MMA(df0, alo[0][kk], bh[2*q], bh[2*q+1]);
                    MMA(df1, alo[1][kk], bh[2*q], bh[2*q+1]);
                }
            }

            // epilogue for this n-tile (cols g0, g0+1; 4 rows per thread)
            const int g0 = nt*8 + 2*tig;
            const float4 ut0 = sU4[g0*2 + 0], uh0 = sU4[g0*2 + 1];
            const float4 ut1 = sU4[g0*2 + 2], uh1 = sU4[g0*2 + 3];
            const uint32_t cbyte = (uint32_t)(g0 * 2);
            {
                const int r = warpM + gq;            // m=0, j=0
                epi(dt0[0], dt0[1], df0[0], df0[1], ut0, uh0, ut1, uh1,
                    cxr[0][0], cyr[0][0], czr[0][0],
                    smem, SWZ((uint32_t)(r*128) + cbyte));
            }
            {
                const int r = warpM + gq + 8;        // m=0, j=1
                epi(dt0[2], dt0[3], df0[2], df0[3], ut0, uh0, ut1, uh1,
                    cxr[0][1], cyr[0][1], czr[0][1],
                    smem, SWZ((uint32_t)(r*128) + cbyte));
            }
            {
                const int r = warpM + 16 + gq;       // m=1, j=0
                epi(dt1[0], dt1[1], df1[0], df1[1], ut0, uh0, ut1, uh1,
                    cxr[1][0], cyr[1][0], czr[1][0],
                    smem, SWZ((uint32_t)(r*128) + cbyte));
            }
            {
                const int r = warpM + 16 + gq + 8;   // m=1, j=1
                epi(dt1[2], dt1[3], df1[2], df1[3], ut0, uh0, ut1, uh1,
                    cxr[1][1], cyr[1][1], czr[1][1],
                    smem, SWZ((uint32_t)(r*128) + cbyte));
            }
        }
    }

    __syncthreads();   // h final visible to readout

    // ---- readout: thread t reads its own row t, v = tanh(Wo h + bo) * 10 ----
    {
        const float* sWo = reinterpret_cast<const float*>(smem + OFF_WO);
        float v0 = 0.f, v1 = 0.f, v2 = 0.f;
        #pragma unroll
        for (int jj = 0; jj < 32; jj++) {
            const uint32_t ho = SWZ((uint32_t)(t*128 + jj*4));
            const float2 fh = __half22float2(
                *reinterpret_cast<const __half2*>(smem + OFF_HHI + ho));
            const float2 fl = __half22float2(
                *reinterpret_cast<const __half2*>(smem + OFF_HLO + ho));
            const float h0 = fh.x + fl.x;
            const float h1 = fh.y + fl.y;
            v0 = fmaf(sWo[      jj*2], h0, fmaf(sWo[      jj*2+1], h1, v0));
            v1 = fmaf(sWo[ 64 + jj*2], h0, fmaf(sWo[ 64 + jj*2+1], h1, v1));
            v2 = fmaf(sWo[128 + jj*2], h0, fmaf(sWo[128 + jj*2+1], h1, v2));
        }
        const int p = blockIdx.x * TPB + t;
        const int b = (p >= N) ? 1 : 0;
        const int n = p - b * N;
        out[(b*3 + 0) * N + n] = tanhf(v0 + __ldg(&b_out[0])) * 10.0f;
        out[(b*3 + 1) * N + n] = tanhf(v1 + __ldg(&b_out[1])) * 10.0f;
        out[(b*3 + 2) * N + n] = tanhf(v2 + __ldg(&b_out[2])) * 10.0f;
    }
}

extern "C" void kernel_launch(void* const* d_in, const int* in_sizes, int n_in,
                              void* d_out, int out_size) {
    const float* coords = (const float*)d_in[0];
    const float* W_h    = (const float*)d_in[1];
    const float* U_h    = (const float*)d_in[2];
    const float* b_h    = (const float*)d_in[3];
    const float* W_tau  = (const float*)d_in[4];
    const float* U_tau  = (const float*)d_in[5];
    const float* b_tau  = (const float*)d_in[6];
    const float* W_out  = (const float*)d_in[7];
    const float* b_out  = (const float*)d_in[8];
    float* out = (float*)d_out;

    const int npts = in_sizes[0] / 3;   // B*N = 221184, divisible by 128
    const int N    = npts / 2;

    cudaFuncSetAttribute(liquid_ode_mma_kernel,
                         cudaFuncAttributeMaxDynamicSharedMemorySize,
                         SMEM_BYTES);

    const int grid = npts / TPB;
    liquid_ode_mma_kernel<<<grid, TPB, SMEM_BYTES>>>(coords,
                                                     W_h, U_h, b_h,
                                                     W_tau, U_tau, b_tau,
                                                     W_out, b_out,
                                                     out, N);
}

// round 9
// speedup vs baseline: 5.4161x; 1.2065x over previous
#include <cuda_runtime.h>
#include <cuda_fp16.h>
#include <cstdint>

#define TPB    128
#define HD     64
#define STEPS  8

// SW128 swizzle (Swizzle<3,4,3>): XOR bits[6:4] with bits[9:7]
#define SWZ(o) ((o) ^ (((o) >> 3) & 0x70u))

// ---------------- SMEM layout (bytes) ----------------
#define OFF_AHI   0        // A operand fp16 [128 r][64] 128B rows swz = 16384
#define OFF_WT    16384    // W_tau fp16 [64 n][64 k] swz                8192
#define OFF_WH    24576    // W_h                                        8192
#define OFF_ST    32768    // h state fp32 [128 r][64+2pad] 264B rows  = 33792
#define ST_ROW    264
#define OFF_U     66560    // per-g {ut.xyz,bt}{uh.xyz,bh} f4x2        = 2048
#define OFF_COORD 68608    // 128 x float4                               2048
#define OFF_WO    70656    // W_out 3x64 f32 = 768, pad 1024
#define SMEM_BYTES 71680

__device__ __forceinline__ uint32_t smem_u32(const void* p) {
    uint32_t a;
    asm("{ .reg .u64 tmp; cvta.to.shared.u64 tmp, %1; cvt.u32.u64 %0, tmp; }"
        : "=r"(a) : "l"(p));
    return a;
}

// fp16 mma.sync (sm_80 baseline ISA, legal on compute_103)
#define MMA(D, A, B0, B1)                                                        \
    asm volatile("mma.sync.aligned.m16n8k16.row.col.f32.f16.f16.f32 "            \
        "{%0,%1,%2,%3}, {%4,%5,%6,%7}, {%8,%9}, {%0,%1,%2,%3};"                  \
        : "+f"((D)[0]), "+f"((D)[1]), "+f"((D)[2]), "+f"((D)[3])                 \
        : "r"((A)[0]), "r"((A)[1]), "r"((A)[2]), "r"((A)[3]),                    \
          "r"(B0), "r"(B1))

#define LDSM_X4(R, addr)                                                         \
    asm volatile("ldmatrix.sync.aligned.m8n8.x4.shared.b16 {%0,%1,%2,%3}, [%4];" \
        : "=r"((R)[0]), "=r"((R)[1]), "=r"((R)[2]), "=r"((R)[3])                 \
        : "r"(addr))

#define TANHF(r, x) asm("tanh.approx.f32 %0, %1;" : "=f"(r) : "f"(x))

// liquid-ODE pointwise update (tau math identical to verified kernels;
// sigmoid via tanh.approx: sigmoid(x) = 0.5 + 0.5*tanh(x/2))
__device__ __forceinline__ float liq(float ta, float fa, float hold)
{
    ta = fminf(fmaxf(ta, -50.0f), 50.0f);
    const float sp   = __logf(1.0f + __expf(ta));
    const float tau  = fmaf(sp, 9.9f, 0.1f);
    float th;  TANHF(th, 0.5f * fa);
    const float fs   = fmaf(0.5f, th, 0.5f);
    const float dh   = fmaf(-hold, __fdividef(1.0f, tau), fs);
    return fmaf(0.125f, dh, hold);
}

// epilogue for one (row, col-pair g0,g0+1):
// u-proj + liquid update; fp32 state read/write + fp16 A writeback
__device__ __forceinline__ void epi(
    float acct0, float acct1, float accf0, float accf1,
    float4 ut0, float4 uh0, float4 ut1, float4 uh1,
    float CX, float CY, float CZ,
    char* smem, uint32_t st_off, uint32_t a_off)
{
    const float ta0 = acct0 + fmaf(ut0.x, CX, fmaf(ut0.y, CY, fmaf(ut0.z, CZ, ut0.w)));
    const float fa0 = accf0 + fmaf(uh0.x, CX, fmaf(uh0.y, CY, fmaf(uh0.z, CZ, uh0.w)));
    const float ta1 = acct1 + fmaf(ut1.x, CX, fmaf(ut1.y, CY, fmaf(ut1.z, CZ, ut1.w)));
    const float fa1 = accf1 + fmaf(uh1.x, CX, fmaf(uh1.y, CY, fmaf(uh1.z, CZ, uh1.w)));

    const float2 hold = *reinterpret_cast<const float2*>(smem + OFF_ST + st_off);
    const float h0n = liq(ta0, fa0, hold.x);
    const float h1n = liq(ta1, fa1, hold.y);

    *reinterpret_cast<float2*>(smem + OFF_ST + st_off) = make_float2(h0n, h1n);
    *reinterpret_cast<__half2*>(smem + OFF_AHI + a_off) = __floats2half2_rn(h0n, h1n);
}

__global__ void __launch_bounds__(TPB, 3) liquid_ode_mma_kernel(
    const float* __restrict__ coords,
    const float* __restrict__ W_h,
    const float* __restrict__ U_h,
    const float* __restrict__ b_h,
    const float* __restrict__ W_tau,
    const float* __restrict__ U_tau,
    const float* __restrict__ b_tau,
    const float* __restrict__ W_out,
    const float* __restrict__ b_out,
    float* __restrict__ out,
    int N)
{
    extern __shared__ char smem[];
    const uint32_t sb = smem_u32(smem);
    const int t    = threadIdx.x;
    const int lane = t & 31;
    const int wid  = t >> 5;
    const int gq   = lane >> 2;   // 0..7
    const int tig  = lane & 3;    // 0..3
    const int warpM = wid * 32;   // this warp's exclusive 32 rows

    // ---- prologue: stage weights (fp16) / U / coords / Wo, zero A + state ----
    for (int idx = t; idx < HD * HD; idx += TPB) {
        const int n = idx >> 6, k = idx & 63;
        const uint32_t sw = SWZ((uint32_t)(n * 128 + k * 2));
        *reinterpret_cast<__half*>(smem + OFF_WT + sw) = __float2half_rn(W_tau[idx]);
        *reinterpret_cast<__half*>(smem + OFF_WH + sw) = __float2half_rn(W_h[idx]);
    }
    if (t < HD) {
        float4* sU = reinterpret_cast<float4*>(smem + OFF_U);
        sU[t*2 + 0] = make_float4(U_tau[t*3+0], U_tau[t*3+1], U_tau[t*3+2], b_tau[t]);
        sU[t*2 + 1] = make_float4(U_h[t*3+0],  U_h[t*3+1],  U_h[t*3+2],  b_h[t]);
    }
    {
        const int p = blockIdx.x * TPB + t;
        reinterpret_cast<float4*>(smem + OFF_COORD)[t] =
            make_float4(coords[3*p], coords[3*p+1], coords[3*p+2], 0.f);
        float* sWo = reinterpret_cast<float*>(smem + OFF_WO);
        for (int i = t; i < 192; i += TPB) sWo[i] = W_out[i];
        uint4 z = make_uint4(0,0,0,0);
        uint4* a4 = reinterpret_cast<uint4*>(smem + OFF_AHI);
        for (int i = t; i < 1024; i += TPB) a4[i] = z;    // A fp16 (16KB)
        uint4* s4 = reinterpret_cast<uint4*>(smem + OFF_ST);
        for (int i = t; i < 2112; i += TPB) s4[i] = z;    // state fp32 (33KB)
    }
    __syncthreads();

    // cache coords of my 4 epilogue rows (fixed all steps)
    float cxr[2][2], cyr[2][2], czr[2][2];
    {
        const float4* sc = reinterpret_cast<const float4*>(smem + OFF_COORD);
        #pragma unroll
        for (int m = 0; m < 2; m++)
            #pragma unroll
            for (int j = 0; j < 2; j++) {
                const float4 c = sc[warpM + m*16 + gq + j*8];
                cxr[m][j] = c.x; cyr[m][j] = c.y; czr[m][j] = c.z;
            }
    }
    const float4* sU4 = reinterpret_cast<const float4*>(smem + OFF_U);

    // ldmatrix lane-address components (constant across steps)
    const int      arow = warpM + (lane & 15);
    const uint32_t acol = (lane & 16) ? 16u : 0u;
    const int      brow = lane & 7;
    const uint32_t bcol = ((lane & 16) ? 32u : 0u) + ((lane & 8) ? 16u : 0u);

    // ---- 8 recurrence steps, warp-private (no block sync in the loop) ----
    #pragma unroll 1
    for (int s = 0; s < STEPS; s++) {
        __syncwarp();   // prior step's cross-lane A writes -> this step's A loads

        // A fragments via ldmatrix.x4: 2 m-tiles x 4 k-tiles (single fp16 term)
        uint32_t ahi[2][4][4];
        #pragma unroll
        for (int m = 0; m < 2; m++) {
            #pragma unroll
            for (int kk = 0; kk < 4; kk++) {
                const uint32_t off =
                    SWZ((uint32_t)((arow + m*16) * 128) + (uint32_t)(kk*32) + acol);
                LDSM_X4(ahi[m][kk], sb + OFF_AHI + off);
            }
        }
        __syncwarp();   // all lanes' A loads done before any lane's epilogue writes

        #pragma unroll 1
        for (int nt = 0; nt < 8; nt++) {
            float dt0[4] = {0.f,0.f,0.f,0.f}, dt1[4] = {0.f,0.f,0.f,0.f};
            float df0[4] = {0.f,0.f,0.f,0.f}, df1[4] = {0.f,0.f,0.f,0.f};

            #pragma unroll
            for (int p2 = 0; p2 < 2; p2++) {   // k-chunk pairs: kk = 2*p2 + q
                const uint32_t off =
                    SWZ((uint32_t)((nt*8 + brow) * 128) + (uint32_t)(p2*64) + bcol);
                uint32_t bt[4], bh[4];
                LDSM_X4(bt, sb + OFF_WT + off);
                LDSM_X4(bh, sb + OFF_WH + off);
                #pragma unroll
                for (int q = 0; q < 2; q++) {
                    const int kk = 2*p2 + q;
                    MMA(dt0, ahi[0][kk], bt[2*q], bt[2*q+1]);
                    MMA(dt1, ahi[1][kk], bt[2*q], bt[2*q+1]);
                    MMA(df0, ahi[0][kk], bh[2*q], bh[2*q+1]);
                    MMA(df1, ahi[1][kk], bh[2*q], bh[2*q+1]);
                }
            }

            // epilogue for this n-tile (cols g0, g0+1; 4 rows per thread)
            const int g0 = nt*8 + 2*tig;
            const float4 ut0 = sU4[g0*2 + 0], uh0 = sU4[g0*2 + 1];
            const float4 ut1 = sU4[g0*2 + 2], uh1 = sU4[g0*2 + 3];
            const uint32_t cbyte  = (uint32_t)(g0 * 2);
            const uint32_t stbyte = (uint32_t)(g0 * 4);
            {
                const int r = warpM + gq;            // m=0, j=0
                epi(dt0[0], dt0[1], df0[0], df0[1], ut0, uh0, ut1, uh1,
                    cxr[0][0], cyr[0][0], czr[0][0], smem,
                    (uint32_t)(r*ST_ROW) + stbyte, SWZ((uint32_t)(r*128) + cbyte));
            }
            {
                const int r = warpM + gq + 8;        // m=0, j=1
                epi(dt0[2], dt0[3], df0[2], df0[3], ut0, uh0, ut1, uh1,
                    cxr[0][1], cyr[0][1], czr[0][1], smem,
                    (uint32_t)(r*ST_ROW) + stbyte, SWZ((uint32_t)(r*128) + cbyte));
            }
            {
                const int r = warpM + 16 + gq;       // m=1, j=0
                epi(dt1[0], dt1[1], df1[0], df1[1], ut0, uh0, ut1, uh1,
                    cxr[1][0], cyr[1][0], czr[1][0], smem,
                    (uint32_t)(r*ST_ROW) + stbyte, SWZ((uint32_t)(r*128) + cbyte));
            }
            {
                const int r = warpM + 16 + gq + 8;   // m=1, j=1
                epi(dt1[2], dt1[3], df1[2], df1[3], ut0, uh0, ut1, uh1,
                    cxr[1][1], cyr[1][1], czr[1][1], smem,
                    (uint32_t)(r*ST_ROW) + stbyte, SWZ((uint32_t)(r*128) + cbyte));
            }
        }
    }

    __syncthreads();   // h final visible to readout

    // ---- readout: thread t reads its own fp32 state row t ----
    {
        const float* sWo = reinterpret_cast<const float*>(smem + OFF_WO);
        float v0 = 0.f, v1 = 0.f, v2 = 0.f;
        #pragma unroll
        for (int jj = 0; jj < 32; jj++) {
            const float2 h2 = *reinterpret_cast<const float2*>(
                smem + OFF_ST + t*ST_ROW + jj*8);
            v0 = fmaf(sWo[      jj*2], h2.x, fmaf(sWo[      jj*2+1], h2.y, v0));
            v1 = fmaf(sWo[ 64 + jj*2], h2.x, fmaf(sWo[ 64 + jj*2+1], h2.y, v1));
            v2 = fmaf(sWo[128 + jj*2], h2.x, fmaf(sWo[128 + jj*2+1], h2.y, v2));
        }
        const int p = blockIdx.x * TPB + t;
        const int b = (p >= N) ? 1 : 0;
        const int n = p - b * N;
        out[(b*3 + 0) * N + n] = tanhf(v0 + __ldg(&b_out[0])) * 10.0f;
        out[(b*3 + 1) * N + n] = tanhf(v1 + __ldg(&b_out[1])) * 10.0f;
        out[(b*3 + 2) * N + n] = tanhf(v2 + __ldg(&b_out[2])) * 10.0f;
    }
}

extern "C" void kernel_launch(void* const* d_in, const int* in_sizes, int n_in,
                              void* d_out, int out_size) {
    const float* coords = (const float*)d_in[0];
    const float* W_h    = (const float*)d_in[1];
    const float* U_h    = (const float*)d_in[2];
    const float* b_h    = (const float*)d_in[3];
    const float* W_tau  = (const float*)d_in[4];
    const float* U_tau  = (const float*)d_in[5];
    const float* b_tau  = (const float*)d_in[6];
    const float* W_out  = (const float*)d_in[7];
    const float* b_out  = (const float*)d_in[8];
    float* out = (float*)d_out;

    const int npts = in_sizes[0] / 3;   // B*N = 221184, divisible by 128
    const int N    = npts / 2;

    cudaFuncSetAttribute(liquid_ode_mma_kernel,
                         cudaFuncAttributeMaxDynamicSharedMemorySize,
                         SMEM_BYTES);

    const int grid = npts / TPB;
    liquid_ode_mma_kernel<<<grid, TPB, SMEM_BYTES>>>(coords,
                                                     W_h, U_h, b_h,
                                                     W_tau, U_tau, b_tau,
                                                     W_out, b_out,
                                                     out, N);
}

// round 10
// speedup vs baseline: 6.6587x; 1.2294x over previous
#include <cuda_runtime.h>
#include <cuda_fp16.h>
#include <cstdint>

#define TPB    128
#define HD     64
#define STEPS  8

// SW128 swizzle (Swizzle<3,4,3>): XOR bits[6:4] with bits[9:7]
#define SWZ(o) ((o) ^ (((o) >> 3) & 0x70u))

// ---------------- SMEM layout (bytes) ----------------
#define OFF_WT    0        // W_tau fp16 [64 n][64 k] swz (128B rows)  = 8192
#define OFF_WH    8192     // W_h                                        8192
#define OFF_UBT   16384    // U_tau|b_tau fp16 [64 n][16 k] (32B rows) = 2048
#define OFF_UBH   18432    // U_h|b_h                                    2048
#define OFF_WO    20480    // W_out 3x64 f32 = 768, pad 1024
#define OFF_COORD 21504    // 128 x float4                               2048
#define OFF_ST    23552    // state {hi2,lo2} 8B x 4096 slots          = 32768
#define SMEM_BYTES 56320

__device__ __forceinline__ uint32_t smem_u32(const void* p) {
    uint32_t a;
    asm("{ .reg .u64 tmp; cvta.to.shared.u64 tmp, %1; cvt.u32.u64 %0, tmp; }"
        : "=r"(a) : "l"(p));
    return a;
}

// fp16 mma.sync (sm_80 baseline ISA, legal on compute_103)
#define MMA(D, A, B0, B1)                                                        \
    asm volatile("mma.sync.aligned.m16n8k16.row.col.f32.f16.f16.f32 "            \
        "{%0,%1,%2,%3}, {%4,%5,%6,%7}, {%8,%9}, {%0,%1,%2,%3};"                  \
        : "+f"((D)[0]), "+f"((D)[1]), "+f"((D)[2]), "+f"((D)[3])                 \
        : "r"((A)[0]), "r"((A)[1]), "r"((A)[2]), "r"((A)[3]),                    \
          "r"(B0), "r"(B1))

#define LDSM_X4(R, addr)                                                         \
    asm volatile("ldmatrix.sync.aligned.m8n8.x4.shared.b16 {%0,%1,%2,%3}, [%4];" \
        : "=r"((R)[0]), "=r"((R)[1]), "=r"((R)[2]), "=r"((R)[3])                 \
        : "r"(addr))

#define LDSM_X2(R, addr)                                                         \
    asm volatile("ldmatrix.sync.aligned.m8n8.x2.shared.b16 {%0,%1}, [%2];"       \
        : "=r"((R)[0]), "=r"((R)[1]) : "r"(addr))

#define TANHF(r, x) asm("tanh.approx.f32 %0, %1;" : "=f"(r) : "f"(x))

// liquid-ODE pointwise update (tau math as verified; sigmoid via tanh.approx)
__device__ __forceinline__ float liq(float ta, float fa, float hold)
{
    ta = fminf(fmaxf(ta, -50.0f), 50.0f);
    const float sp   = __logf(1.0f + __expf(ta));
    const float tau  = fmaf(sp, 9.9f, 0.1f);
    float th;  TANHF(th, 0.5f * fa);
    const float fs   = fmaf(0.5f, th, 0.5f);
    const float dh   = fmaf(-hold, __fdividef(1.0f, tau), fs);
    return fmaf(0.125f, dh, hold);
}

// epilogue for one (row, col-pair): D accumulators already include the
// u-projection (folded into MMA via augmented K). State slot = {hi2, lo2}.
// Returns the packed fp16 pair = next step's A-fragment register half.
__device__ __forceinline__ uint32_t epi2(
    float ta0, float ta1, float fa0, float fa1,
    char* smem, uint32_t soff)
{
    const uint2 slot = *reinterpret_cast<const uint2*>(smem + soff);
    const float2 fh = __half22float2(*reinterpret_cast<const __half2*>(&slot.x));
    const float2 fl = __half22float2(*reinterpret_cast<const __half2*>(&slot.y));
    const float h0n = liq(ta0, fa0, fh.x + fl.x);
    const float h1n = liq(ta1, fa1, fh.y + fl.y);
    __half2 hp = __floats2half2_rn(h0n, h1n);
    const float2 hb = __half22float2(hp);
    __half2 lp = __floats2half2_rn(h0n - hb.x, h1n - hb.y);
    uint2 ns;
    ns.x = *reinterpret_cast<uint32_t*>(&hp);
    ns.y = *reinterpret_cast<uint32_t*>(&lp);
    *reinterpret_cast<uint2*>(smem + soff) = ns;
    return ns.x;
}

// one recurrence step: MMAs read acur, epilogues write anx (+ state SMEM)
__device__ __forceinline__ void do_step(
    char* smem, uint32_t sb,
    uint32_t (&acur)[2][4][4], uint32_t (&anx)[2][4][4],
    const uint32_t (&acoord)[2][4],
    int lane, int wid)
{
    const uint32_t brow = (uint32_t)(lane & 7);
    const uint32_t bcol = ((lane & 16) ? 32u : 0u) + ((lane & 8) ? 16u : 0u);
    const uint32_t ubb  = sb + (uint32_t)((lane & 7) * 32) + ((lane & 8) ? 16u : 0u);
    const uint32_t stb  = (uint32_t)(OFF_ST + wid*1024 + lane*8);

    #pragma unroll
    for (int nt = 0; nt < 8; nt++) {
        float dt0[4] = {0,0,0,0}, dt1[4] = {0,0,0,0};
        float df0[4] = {0,0,0,0}, df1[4] = {0,0,0,0};

        #pragma unroll
        for (int p2 = 0; p2 < 2; p2++) {
            const uint32_t off =
                SWZ((uint32_t)((nt*8 + brow) * 128) + (uint32_t)(p2*64) + bcol);
            uint32_t bt[4], bh[4];
            LDSM_X4(bt, sb + OFF_WT + off);
            LDSM_X4(bh, sb + OFF_WH + off);
            #pragma unroll
            for (int q = 0; q < 2; q++) {
                const int kk = 2*p2 + q;
                MMA(dt0, acur[0][kk], bt[2*q], bt[2*q+1]);
                MMA(dt1, acur[1][kk], bt[2*q], bt[2*q+1]);
                MMA(df0, acur[0][kk], bh[2*q], bh[2*q+1]);
                MMA(df1, acur[1][kk], bh[2*q], bh[2*q+1]);
            }
        }
        // augmented-K chunk: A = (cx,cy,cz,1,0...), B = (U|b|0...) rows
        {
            uint32_t ubt[2], ubh[2];
            LDSM_X2(ubt, ubb + OFF_UBT + (uint32_t)(nt*256));
            LDSM_X2(ubh, ubb + OFF_UBH + (uint32_t)(nt*256));
            MMA(dt0, acoord[0], ubt[0], ubt[1]);
            MMA(dt1, acoord[1], ubt[0], ubt[1]);
            MMA(df0, acoord[0], ubh[0], ubh[1]);
            MMA(df1, acoord[1], ubh[0], ubh[1]);
        }

        // epilogues: conflict-free state slots; outputs ARE next A fragments
        const uint32_t sbase = stb + (uint32_t)(nt*4096);
        anx[0][nt>>1][(nt&1)*2 + 0] = epi2(dt0[0], dt0[1], df0[0], df0[1], smem, sbase + 0);
        anx[0][nt>>1][(nt&1)*2 + 1] = epi2(dt0[2], dt0[3], df0[2], df0[3], smem, sbase + 256);
        anx[1][nt>>1][(nt&1)*2 + 0] = epi2(dt1[0], dt1[1], df1[0], df1[1], smem, sbase + 512);
        anx[1][nt>>1][(nt&1)*2 + 1] = epi2(dt1[2], dt1[3], df1[2], df1[3], smem, sbase + 768);
    }
}

__global__ void __launch_bounds__(TPB, 3) liquid_ode_mma_kernel(
    const float* __restrict__ coords,
    const float* __restrict__ W_h,
    const float* __restrict__ U_h,
    const float* __restrict__ b_h,
    const float* __restrict__ W_tau,
    const float* __restrict__ U_tau,
    const float* __restrict__ b_tau,
    const float* __restrict__ W_out,
    const float* __restrict__ b_out,
    float* __restrict__ out,
    int N)
{
    extern __shared__ char smem[];
    const uint32_t sb = smem_u32(smem);
    const int t    = threadIdx.x;
    const int lane = t & 31;
    const int wid  = t >> 5;
    const int gq   = lane >> 2;
    const int tig  = lane & 3;
    const int warpM = wid * 32;

    // ---- prologue ----
    for (int idx = t; idx < HD * HD; idx += TPB) {
        const int n = idx >> 6, k = idx & 63;
        const uint32_t sw = SWZ((uint32_t)(n * 128 + k * 2));
        *reinterpret_cast<__half*>(smem + OFF_WT + sw) = __float2half_rn(W_tau[idx]);
        *reinterpret_cast<__half*>(smem + OFF_WH + sw) = __float2half_rn(W_h[idx]);
    }
    for (int idx = t; idx < HD * 16; idx += TPB) {
        const int n = idx >> 4, k = idx & 15;
        float vt = 0.f, vh = 0.f;
        if (k < 3)       { vt = U_tau[n*3 + k]; vh = U_h[n*3 + k]; }
        else if (k == 3) { vt = b_tau[n];       vh = b_h[n]; }
        *reinterpret_cast<__half*>(smem + OFF_UBT + idx*2) = __float2half_rn(vt);
        *reinterpret_cast<__half*>(smem + OFF_UBH + idx*2) = __float2half_rn(vh);
    }
    {
        const int p = blockIdx.x * TPB + t;
        reinterpret_cast<float4*>(smem + OFF_COORD)[t] =
            make_float4(coords[3*p], coords[3*p+1], coords[3*p+2], 0.f);
        float* sWo = reinterpret_cast<float*>(smem + OFF_WO);
        for (int i = t; i < 192; i += TPB) sWo[i] = W_out[i];
        uint2* s2 = reinterpret_cast<uint2*>(smem + OFF_ST);
        for (int i = t; i < 4096; i += TPB) s2[i] = make_uint2(0u, 0u);   // h = 0
    }
    __syncthreads();

    // constant A-fragment regs for the augmented-K chunk: cols (cx,cy,cz,1,0..)
    uint32_t acoord[2][4];
    {
        const float4* sc = reinterpret_cast<const float4*>(smem + OFF_COORD);
        #pragma unroll
        for (int m = 0; m < 2; m++) {
            const float4 c0 = sc[warpM + m*16 + gq];
            const float4 c1 = sc[warpM + m*16 + gq + 8];
            uint32_t p0 = 0u, p1 = 0u;
            if (tig == 0) {
                __half2 h0 = __floats2half2_rn(c0.x, c0.y);
                __half2 h1 = __floats2half2_rn(c1.x, c1.y);
                p0 = *reinterpret_cast<uint32_t*>(&h0);
                p1 = *reinterpret_cast<uint32_t*>(&h1);
            } else if (tig == 1) {
                __half2 h0 = __floats2half2_rn(c0.z, 1.0f);
                __half2 h1 = __floats2half2_rn(c1.z, 1.0f);
                p0 = *reinterpret_cast<uint32_t*>(&h0);
                p1 = *reinterpret_cast<uint32_t*>(&h1);
            }
            acoord[m][0] = p0;
            acoord[m][1] = p1;
            acoord[m][2] = 0u;
            acoord[m][3] = 0u;
        }
    }

    // A double buffer (h fp16), register-resident; h0 = 0
    uint32_t a0[2][4][4], a1[2][4][4];
    #pragma unroll
    for (int m = 0; m < 2; m++)
        #pragma unroll
        for (int kk = 0; kk < 4; kk++)
            #pragma unroll
            for (int j = 0; j < 4; j++) { a0[m][kk][j] = 0u; a1[m][kk][j] = 0u; }

    // ---- 8 steps, fully sync-free (state + A are thread-private) ----
    #pragma unroll 1
    for (int s = 0; s < STEPS; s++) {
        do_step(smem, sb, a0, a1, acoord, lane, wid);
        #pragma unroll
        for (int m = 0; m < 2; m++)
            #pragma unroll
            for (int kk = 0; kk < 4; kk++)
                #pragma unroll
                for (int j = 0; j < 4; j++) a0[m][kk][j] = a1[m][kk][j];
    }

    __syncwarp();   // state rows are warp-private; cross-lane writes -> readout

    // ---- readout: thread t reads its own row t from state (hi+lo) ----
    {
        const float* sWo = reinterpret_cast<const float*>(smem + OFF_WO);
        float v0 = 0.f, v1 = 0.f, v2 = 0.f;
        #pragma unroll
        for (int gp = 0; gp < 32; gp++) {
            const uint32_t soff = (uint32_t)(OFF_ST + (gp>>2)*4096 + (t>>3)*256
                                             + (t&7)*32 + (gp&3)*8);
            const uint2 slot = *reinterpret_cast<const uint2*>(smem + soff);
            const float2 fh = __half22float2(*reinterpret_cast<const __half2*>(&slot.x));
            const float2 fl = __half22float2(*reinterpret_cast<const __half2*>(&slot.y));
            const float h0 = fh.x + fl.x;
            const float h1 = fh.y + fl.y;
            v0 = fmaf(sWo[      gp*2], h0, fmaf(sWo[      gp*2+1], h1, v0));
            v1 = fmaf(sWo[ 64 + gp*2], h0, fmaf(sWo[ 64 + gp*2+1], h1, v1));
            v2 = fmaf(sWo[128 + gp*2], h0, fmaf(sWo[128 + gp*2+1], h1, v2));
        }
        const int p = blockIdx.x * TPB + t;
        const int b = (p >= N) ? 1 : 0;
        const int n = p - b * N;
        out[(b*3 + 0) * N + n] = tanhf(v0 + __ldg(&b_out[0])) * 10.0f;
        out[(b*3 + 1) * N + n] = tanhf(v1 + __ldg(&b_out[1])) * 10.0f;
        out[(b*3 + 2) * N + n] = tanhf(v2 + __ldg(&b_out[2])) * 10.0f;
    }
}

extern "C" void kernel_launch(void* const* d_in, const int* in_sizes, int n_in,
                              void* d_out, int out_size) {
    const float* coords = (const float*)d_in[0];
    const float* W_h    = (const float*)d_in[1];
    const float* U_h    = (const float*)d_in[2];
    const float* b_h    = (const float*)d_in[3];
    const float* W_tau  = (const float*)d_in[4];
    const float* U_tau  = (const float*)d_in[5];
    const float* b_tau  = (const float*)d_in[6];
    const float* W_out  = (const float*)d_in[7];
    const float* b_out  = (const float*)d_in[8];
    float* out = (float*)d_out;

    const int npts = in_sizes[0] / 3;   // B*N = 221184, divisible by 128
    const int N    = npts / 2;

    cudaFuncSetAttribute(liquid_ode_mma_kernel,
                         cudaFuncAttributeMaxDynamicSharedMemorySize,
                         SMEM_BYTES);

    const int grid = npts / TPB;
    liquid_ode_mma_kernel<<<grid, TPB, SMEM_BYTES>>>(coords,
                                                     W_h, U_h, b_h,
                                                     W_tau, U_tau, b_tau,
                                                     W_out, b_out,
                                                     out, N);
}

// round 11
// speedup vs baseline: 6.9477x; 1.0434x over previous
#include <cuda_runtime.h>
#include <cuda_fp16.h>
#include <cstdint>

#define TPB    128
#define HD     64
#define STEPS  8

// SW128 swizzle (Swizzle<3,4,3>): XOR bits[6:4] with bits[9:7]
#define SWZ(o) ((o) ^ (((o) >> 3) & 0x70u))

// ---------------- SMEM layout (bytes) ----------------
#define OFF_WT    0        // W_tau fp16 [64 n][64 k] swz (128B rows)  = 8192
#define OFF_WH    8192     // W_h                                        8192
#define OFF_UBT   16384    // U_tau|b_tau fp16 [64 n][16 k] (32B rows) = 2048
#define OFF_UBH   18432    // U_h|b_h                                    2048
#define OFF_WO    20480    // W_out 3x64 f32 = 768, pad 1024
#define OFF_COORD 21504    // 128 x float4                               2048
#define OFF_ST    23552    // state fp32 float2 x 4096 slots           = 32768
#define SMEM_BYTES 56320

__device__ __forceinline__ uint32_t smem_u32(const void* p) {
    uint32_t a;
    asm("{ .reg .u64 tmp; cvta.to.shared.u64 tmp, %1; cvt.u32.u64 %0, tmp; }"
        : "=r"(a) : "l"(p));
    return a;
}

// fp16 mma.sync (sm_80 baseline ISA, legal on compute_103)
#define MMA(D, A, B0, B1)                                                        \
    asm volatile("mma.sync.aligned.m16n8k16.row.col.f32.f16.f16.f32 "            \
        "{%0,%1,%2,%3}, {%4,%5,%6,%7}, {%8,%9}, {%0,%1,%2,%3};"                  \
        : "+f"((D)[0]), "+f"((D)[1]), "+f"((D)[2]), "+f"((D)[3])                 \
        : "r"((A)[0]), "r"((A)[1]), "r"((A)[2]), "r"((A)[3]),                    \
          "r"(B0), "r"(B1))

#define LDSM_X4(R, addr)                                                         \
    asm volatile("ldmatrix.sync.aligned.m8n8.x4.shared.b16 {%0,%1,%2,%3}, [%4];" \
        : "=r"((R)[0]), "=r"((R)[1]), "=r"((R)[2]), "=r"((R)[3])                 \
        : "r"(addr))

#define LDSM_X2(R, addr)                                                         \
    asm volatile("ldmatrix.sync.aligned.m8n8.x2.shared.b16 {%0,%1}, [%2];"       \
        : "=r"((R)[0]), "=r"((R)[1]) : "r"(addr))

#define TANHF(r, x) asm("tanh.approx.f32 %0, %1;" : "=f"(r) : "f"(x))

// liquid-ODE pointwise update (tau math as verified; sigmoid via tanh.approx)
__device__ __forceinline__ float liq(float ta, float fa, float hold)
{
    ta = fminf(fmaxf(ta, -50.0f), 50.0f);
    const float sp   = __logf(1.0f + __expf(ta));
    const float tau  = fmaf(sp, 9.9f, 0.1f);
    float th;  TANHF(th, 0.5f * fa);
    const float fs   = fmaf(0.5f, th, 0.5f);
    const float dh   = fmaf(-hold, __fdividef(1.0f, tau), fs);
    return fmaf(0.125f, dh, hold);
}

// epilogue for one (row, col-pair). State slot is plain fp32 float2
// (lane-private). Returns packed fp16 pair = next step's A-fragment half.
__device__ __forceinline__ uint32_t epi2(
    float ta0, float ta1, float fa0, float fa1,
    char* smem, uint32_t soff)
{
    const float2 hold = *reinterpret_cast<const float2*>(smem + soff);
    const float h0n = liq(ta0, fa0, hold.x);
    const float h1n = liq(ta1, fa1, hold.y);
    *reinterpret_cast<float2*>(smem + soff) = make_float2(h0n, h1n);
    __half2 hp = __floats2half2_rn(h0n, h1n);
    return *reinterpret_cast<uint32_t*>(&hp);
}

// one recurrence step: MMAs read acur, epilogues write anx (+ state SMEM).
// All ldmatrix addresses are precomputed (constant across steps).
__device__ __forceinline__ void do_step(
    char* smem,
    const uint32_t (&acur)[2][4][4], uint32_t (&anx)[2][4][4],
    const uint32_t (&acoord)[2][4],
    const uint32_t (&boffT)[8][2],
    uint32_t ubbT, uint32_t stb)
{
    #pragma unroll
    for (int nt = 0; nt < 8; nt++) {
        float dt0[4] = {0,0,0,0}, dt1[4] = {0,0,0,0};
        float df0[4] = {0,0,0,0}, df1[4] = {0,0,0,0};

        #pragma unroll
        for (int p2 = 0; p2 < 2; p2++) {
            uint32_t bt[4], bh[4];
            LDSM_X4(bt, boffT[nt][p2]);
            LDSM_X4(bh, boffT[nt][p2] + 8192u);   // W_h mirrors W_tau layout
            #pragma unroll
            for (int q = 0; q < 2; q++) {
                const int kk = 2*p2 + q;
                MMA(dt0, acur[0][kk], bt[2*q], bt[2*q+1]);
                MMA(dt1, acur[1][kk], bt[2*q], bt[2*q+1]);
                MMA(df0, acur[0][kk], bh[2*q], bh[2*q+1]);
                MMA(df1, acur[1][kk], bh[2*q], bh[2*q+1]);
            }
        }
        // augmented-K chunk: A = (cx,cy,cz,1,0...), B = (U|b|0...) rows
        {
            uint32_t ubt[2], ubh[2];
            LDSM_X2(ubt, ubbT + (uint32_t)(nt*256));
            LDSM_X2(ubh, ubbT + (uint32_t)(nt*256) + 2048u);
            MMA(dt0, acoord[0], ubt[0], ubt[1]);
            MMA(dt1, acoord[1], ubt[0], ubt[1]);
            MMA(df0, acoord[0], ubh[0], ubh[1]);
            MMA(df1, acoord[1], ubh[0], ubh[1]);
        }

        // epilogues: lane-private fp32 state; outputs ARE next A fragments
        const uint32_t sbase = stb + (uint32_t)(nt*4096);
        anx[0][nt>>1][(nt&1)*2 + 0] = epi2(dt0[0], dt0[1], df0[0], df0[1], smem, sbase + 0);
        anx[0][nt>>1][(nt&1)*2 + 1] = epi2(dt0[2], dt0[3], df0[2], df0[3], smem, sbase + 256);
        anx[1][nt>>1][(nt&1)*2 + 0] = epi2(dt1[0], dt1[1], df1[0], df1[1], smem, sbase + 512);
        anx[1][nt>>1][(nt&1)*2 + 1] = epi2(dt1[2], dt1[3], df1[2], df1[3], smem, sbase + 768);
    }
}

__global__ void __launch_bounds__(TPB, 3) liquid_ode_mma_kernel(
    const float* __restrict__ coords,
    const float* __restrict__ W_h,
    const float* __restrict__ U_h,
    const float* __restrict__ b_h,
    const float* __restrict__ W_tau,
    const float* __restrict__ U_tau,
    const float* __restrict__ b_tau,
    const float* __restrict__ W_out,
    const float* __restrict__ b_out,
    float* __restrict__ out,
    int N)
{
    extern __shared__ char smem[];
    const uint32_t sb = smem_u32(smem);
    const int t    = threadIdx.x;
    const int lane = t & 31;
    const int wid  = t >> 5;
    const int gq   = lane >> 2;
    const int tig  = lane & 3;
    const int warpM = wid * 32;

    // ---- prologue ----
    for (int idx = t; idx < HD * HD; idx += TPB) {
        const int n = idx >> 6, k = idx & 63;
        const uint32_t sw = SWZ((uint32_t)(n * 128 + k * 2));
        *reinterpret_cast<__half*>(smem + OFF_WT + sw) = __float2half_rn(W_tau[idx]);
        *reinterpret_cast<__half*>(smem + OFF_WH + sw) = __float2half_rn(W_h[idx]);
    }
    for (int idx = t; idx < HD * 16; idx += TPB) {
        const int n = idx >> 4, k = idx & 15;
        float vt = 0.f, vh = 0.f;
        if (k < 3)       { vt = U_tau[n*3 + k]; vh = U_h[n*3 + k]; }
        else if (k == 3) { vt = b_tau[n];       vh = b_h[n]; }
        *reinterpret_cast<__half*>(smem + OFF_UBT + idx*2) = __float2half_rn(vt);
        *reinterpret_cast<__half*>(smem + OFF_UBH + idx*2) = __float2half_rn(vh);
    }
    {
        const int p = blockIdx.x * TPB + t;
        reinterpret_cast<float4*>(smem + OFF_COORD)[t] =
            make_float4(coords[3*p], coords[3*p+1], coords[3*p+2], 0.f);
        float* sWo = reinterpret_cast<float*>(smem + OFF_WO);
        for (int i = t; i < 192; i += TPB) sWo[i] = W_out[i];
        float2* s2 = reinterpret_cast<float2*>(smem + OFF_ST);
        for (int i = t; i < 4096; i += TPB) s2[i] = make_float2(0.f, 0.f);   // h = 0
    }
    __syncthreads();

    // constant A-fragment regs for the augmented-K chunk: cols (cx,cy,cz,1,0..)
    uint32_t acoord[2][4];
    {
        const float4* sc = reinterpret_cast<const float4*>(smem + OFF_COORD);
        #pragma unroll
        for (int m = 0; m < 2; m++) {
            const float4 c0 = sc[warpM + m*16 + gq];
            const float4 c1 = sc[warpM + m*16 + gq + 8];
            uint32_t p0 = 0u, p1 = 0u;
            if (tig == 0) {
                __half2 h0 = __floats2half2_rn(c0.x, c0.y);
                __half2 h1 = __floats2half2_rn(c1.x, c1.y);
                p0 = *reinterpret_cast<uint32_t*>(&h0);
                p1 = *reinterpret_cast<uint32_t*>(&h1);
            } else if (tig == 1) {
                __half2 h0 = __floats2half2_rn(c0.z, 1.0f);
                __half2 h1 = __floats2half2_rn(c1.z, 1.0f);
                p0 = *reinterpret_cast<uint32_t*>(&h0);
                p1 = *reinterpret_cast<uint32_t*>(&h1);
            }
            acoord[m][0] = p0;
            acoord[m][1] = p1;
            acoord[m][2] = 0u;
            acoord[m][3] = 0u;
        }
    }

    // precomputed ldmatrix addresses (constant across all steps)
    uint32_t boffT[8][2];
    {
        const uint32_t brow = (uint32_t)(lane & 7);
        const uint32_t bcol = ((lane & 16) ? 32u : 0u) + ((lane & 8) ? 16u : 0u);
        #pragma unroll
        for (int nt = 0; nt < 8; nt++)
            #pragma unroll
            for (int p2 = 0; p2 < 2; p2++)
                boffT[nt][p2] = sb + OFF_WT +
                    SWZ((uint32_t)((nt*8 + brow) * 128) + (uint32_t)(p2*64) + bcol);
    }
    const uint32_t ubbT = sb + OFF_UBT + (uint32_t)((lane & 7) * 32)
                        + ((lane & 8) ? 16u : 0u);
    const uint32_t stb  = (uint32_t)(OFF_ST + wid*1024 + lane*8);

    // A double buffer (h fp16), register-resident; h0 = 0
    uint32_t a0[2][4][4], a1[2][4][4];
    #pragma unroll
    for (int m = 0; m < 2; m++)
        #pragma unroll
        for (int kk = 0; kk < 4; kk++)
            #pragma unroll
            for (int j = 0; j < 4; j++) { a0[m][kk][j] = 0u; a1[m][kk][j] = 0u; }

    // ---- 8 steps, sync-free, ping-pong A buffers (no copy) ----
    #pragma unroll 1
    for (int s = 0; s < STEPS / 2; s++) {
        do_step(smem, a0, a1, acoord, boffT, ubbT, stb);
        do_step(smem, a1, a0, acoord, boffT, ubbT, stb);
    }

    __syncwarp();   // state rows are warp-private; cross-lane writes -> readout

    // ---- readout: thread t reads its own row t from fp32 state ----
    {
        const float* sWo = reinterpret_cast<const float*>(smem + OFF_WO);
        float v0 = 0.f, v1 = 0.f, v2 = 0.f;
        #pragma unroll
        for (int gp = 0; gp < 32; gp++) {
            const uint32_t soff = (uint32_t)(OFF_ST + (gp>>2)*4096 + (t>>3)*256
                                             + (t&7)*32 + (gp&3)*8);
            const float2 h2 = *reinterpret_cast<const float2*>(smem + soff);
            v0 = fmaf(sWo[      gp*2], h2.x, fmaf(sWo[      gp*2+1], h2.y, v0));
            v1 = fmaf(sWo[ 64 + gp*2], h2.x, fmaf(sWo[ 64 + gp*2+1], h2.y, v1));
            v2 = fmaf(sWo[128 + gp*2], h2.x, fmaf(sWo[128 + gp*2+1], h2.y, v2));
        }
        const int p = blockIdx.x * TPB + t;
        const int b = (p >= N) ? 1 : 0;
        const int n = p - b * N;
        out[(b*3 + 0) * N + n] = tanhf(v0 + __ldg(&b_out[0])) * 10.0f;
        out[(b*3 + 1) * N + n] = tanhf(v1 + __ldg(&b_out[1])) * 10.0f;
        out[(b*3 + 2) * N + n] = tanhf(v2 + __ldg(&b_out[2])) * 10.0f;
    }
}

extern "C" void kernel_launch(void* const* d_in, const int* in_sizes, int n_in,
                              void* d_out, int out_size) {
    const float* coords = (const float*)d_in[0];
    const float* W_h    = (const float*)d_in[1];
    const float* U_h    = (const float*)d_in[2];
    const float* b_h    = (const float*)d_in[3];
    const float* W_tau  = (const float*)d_in[4];
    const float* U_tau  = (const float*)d_in[5];
    const float* b_tau  = (const float*)d_in[6];
    const float* W_out  = (const float*)d_in[7];
    const float* b_out  = (const float*)d_in[8];
    float* out = (float*)d_out;

    const int npts = in_sizes[0] / 3;   // B*N = 221184, divisible by 128
    const int N    = npts / 2;

    cudaFuncSetAttribute(liquid_ode_mma_kernel,
                         cudaFuncAttributeMaxDynamicSharedMemorySize,
                         SMEM_BYTES);

    const int grid = npts / TPB;
    liquid_ode_mma_kernel<<<grid, TPB, SMEM_BYTES>>>(coords,
                                                     W_h, U_h, b_h,
                                                     W_tau, U_tau, b_tau,
                                                     W_out, b_out,
                                                     out, N);
}